// round 3
// baseline (speedup 1.0000x reference)
#include <cuda_runtime.h>
#include <math.h>
#include <stdint.h>

// Problem constants
#define BATCH 32
#define NTOK  784
#define DIM   512
#define NH    8
#define HD    64
#define HH    28
#define WW    28
#define DA    49

// -------- scratch (__device__ globals; no allocations allowed) --------
__device__ float    g_q    [BATCH * NTOK * DIM];
__device__ float    g_kv   [BATCH * NTOK * 2 * DIM];   // k at +0, v at +512 within 1024-stride row
__device__ float    g_agent[BATCH * DA * DIM];
__device__ float    g_agent_v[BATCH * NH * DA * HD];
__device__ float    g_pos_bias[NH * DA * NTOK];        // [h,a,n]
__device__ float    g_agent_bias[NH * NTOK * DA];      // [h,n,a]
__device__ float    g_attn [BATCH * NTOK * DIM];       // float attn+dwc staging
// tf32 (pre-converted) operands for tensor-core GEMMs
__device__ uint32_t g_xt   [BATCH * NTOK * DIM];
__device__ uint32_t g_qw_t [DIM * DIM];
__device__ uint32_t g_kvw_t[2 * DIM * DIM];
__device__ uint32_t g_pw_t [DIM * DIM];
__device__ uint32_t g_attn_t[BATCH * NTOK * DIM];

__device__ __forceinline__ uint32_t f2tf(float f) {
    uint32_t u;
    asm("cvt.rna.tf32.f32 %0, %1;" : "=r"(u) : "f"(f));
    return u;
}

// ======================= fp32 -> tf32 conversion pass =======================
__global__ void cvt_tf32_kernel(const float4* __restrict__ in, uint4* __restrict__ out, int n4)
{
    int i = blockIdx.x * blockDim.x + threadIdx.x;
    if (i < n4) {
        float4 v = in[i];
        uint4 o;
        o.x = f2tf(v.x); o.y = f2tf(v.y); o.z = f2tf(v.z); o.w = f2tf(v.w);
        out[i] = o;
    }
}

// ======================= TF32 tensor-core GEMM, cp.async 4-stage =======================
// C[M,N] = A[M,K] @ W[N,K]^T (+bias). BM=BN=128, BK=16, 4 stages, 256 thr = 8 warps (2x4),
// warp tile 64x32 = 4x4 of mma.m16n8k8. Stage tile: [128][20] padded (conflict-free frags).

#define GSTAGES 4
#define STAGE_ELEMS (2 * 128 * 20)           // A tile + B tile per stage
#define GEMM_SMEM_BYTES (GSTAGES * STAGE_ELEMS * 4)   // 81920

__device__ __forceinline__ void cp_async16(uint32_t saddr, const void* gptr) {
    asm volatile("cp.async.ca.shared.global [%0], [%1], 16;" :: "r"(saddr), "l"(gptr));
}
__device__ __forceinline__ void cp_commit() {
    asm volatile("cp.async.commit_group;");
}
template<int N> __device__ __forceinline__ void cp_wait() {
    asm volatile("cp.async.wait_group %0;" :: "n"(N));
}

__device__ __forceinline__ void mma_tf32(float* d, const uint32_t* a, const uint32_t* b) {
    asm volatile(
        "mma.sync.aligned.m16n8k8.row.col.f32.tf32.tf32.f32 "
        "{%0,%1,%2,%3}, {%4,%5,%6,%7}, {%8,%9}, {%0,%1,%2,%3};"
        : "+f"(d[0]), "+f"(d[1]), "+f"(d[2]), "+f"(d[3])
        : "r"(a[0]), "r"(a[1]), "r"(a[2]), "r"(a[3]), "r"(b[0]), "r"(b[1]));
}

__device__ __forceinline__ void tf32_gemm_body(const uint32_t* __restrict__ A,
                                               const uint32_t* __restrict__ W,
                                               float* __restrict__ C,
                                               const float* __restrict__ bias,
                                               int K, int ldc)
{
    extern __shared__ uint32_t dsm[];
    const int row0 = blockIdx.y * 128;
    const int col0 = blockIdx.x * 128;
    const int tid  = threadIdx.x;
    const int lane = tid & 31;
    const int warp = tid >> 5;
    const int wm = warp >> 2;            // 0..1 -> 64-row slab
    const int wn = warp & 3;             // 0..3 -> 32-col slab
    const int gid = lane >> 2;           // 0..7
    const int tig = lane & 3;            // 0..3

    const int lr = tid >> 1;             // 0..127 (load row)
    const int lc = (tid & 1) * 8;        // 0 or 8

    const uint32_t* Ag = A + (size_t)(row0 + lr) * K + lc;
    const uint32_t* Wg = W + (size_t)(col0 + lr) * K + lc;

    uint32_t smem_base;
    {
        uint64_t p = __cvta_generic_to_shared(dsm);
        smem_base = (uint32_t)p;
    }
    const uint32_t a_dst = smem_base + (uint32_t)(lr * 20 + lc) * 4;
    const uint32_t b_dst = a_dst + 128 * 20 * 4;

    const int NITER = K >> 4;

    float acc[4][4][4];
#pragma unroll
    for (int i = 0; i < 4; i++)
#pragma unroll
        for (int j = 0; j < 4; j++)
#pragma unroll
            for (int r = 0; r < 4; r++) acc[i][j][r] = 0.f;

    // prologue: stages 0..2
#pragma unroll
    for (int s = 0; s < GSTAGES - 1; s++) {
        uint32_t so = (uint32_t)(s * STAGE_ELEMS) * 4;
        cp_async16(a_dst + so,      Ag + s * 16);
        cp_async16(a_dst + so + 16, Ag + s * 16 + 4);
        cp_async16(b_dst + so,      Wg + s * 16);
        cp_async16(b_dst + so + 16, Wg + s * 16 + 4);
        cp_commit();
    }

    for (int it = 0; it < NITER; it++) {
        cp_wait<GSTAGES - 2>();
        __syncthreads();

        int nxt = it + GSTAGES - 1;
        if (nxt < NITER) {
            int s = nxt & (GSTAGES - 1);
            uint32_t so = (uint32_t)(s * STAGE_ELEMS) * 4;
            cp_async16(a_dst + so,      Ag + nxt * 16);
            cp_async16(a_dst + so + 16, Ag + nxt * 16 + 4);
            cp_async16(b_dst + so,      Wg + nxt * 16);
            cp_async16(b_dst + so + 16, Wg + nxt * 16 + 4);
        }
        cp_commit();

        const uint32_t* As = dsm + (it & (GSTAGES - 1)) * STAGE_ELEMS;
        const uint32_t* Bs = As + 128 * 20;

#pragma unroll
        for (int kk = 0; kk < 16; kk += 8) {
            uint32_t af[4][4], bf[4][2];
#pragma unroll
            for (int mt = 0; mt < 4; mt++) {
                int r = wm * 64 + mt * 16 + gid;
                af[mt][0] = As[r * 20 + kk + tig];
                af[mt][1] = As[(r + 8) * 20 + kk + tig];
                af[mt][2] = As[r * 20 + kk + tig + 4];
                af[mt][3] = As[(r + 8) * 20 + kk + tig + 4];
            }
#pragma unroll
            for (int nt = 0; nt < 4; nt++) {
                int cb = wn * 32 + nt * 8 + gid;
                bf[nt][0] = Bs[cb * 20 + kk + tig];
                bf[nt][1] = Bs[cb * 20 + kk + tig + 4];
            }
#pragma unroll
            for (int mt = 0; mt < 4; mt++)
#pragma unroll
                for (int nt = 0; nt < 4; nt++)
                    mma_tf32(acc[mt][nt], af[mt], bf[nt]);
        }
    }

#pragma unroll
    for (int mt = 0; mt < 4; mt++) {
        int r = row0 + wm * 64 + mt * 16 + gid;
#pragma unroll
        for (int nt = 0; nt < 4; nt++) {
            int c = col0 + wn * 32 + nt * 8 + 2 * tig;
            float2 v0 = make_float2(acc[mt][nt][0], acc[mt][nt][1]);
            float2 v1 = make_float2(acc[mt][nt][2], acc[mt][nt][3]);
            if (bias) {
                float2 bb = *(const float2*)&bias[c];
                v0.x += bb.x; v0.y += bb.y;
                v1.x += bb.x; v1.y += bb.y;
            }
            *(float2*)&C[(size_t)r * ldc + c]       = v0;
            *(float2*)&C[(size_t)(r + 8) * ldc + c] = v1;
        }
    }
}

__global__ void gemm_q() {
    tf32_gemm_body(g_xt, g_qw_t, g_q, nullptr, DIM, DIM);
}
__global__ void gemm_kv() {
    tf32_gemm_body(g_xt, g_kvw_t, g_kv, nullptr, DIM, 2 * DIM);
}
__global__ void gemm_proj(const float* __restrict__ b, float* __restrict__ out) {
    tf32_gemm_body(g_attn_t, g_pw_t, out, b, DIM, DIM);
}

// ======================= agent = 4x4 avg pool of q image =======================
__global__ void pool_agent()
{
    int ba = blockIdx.x;              // b*49 + a
    int b = ba / DA, a = ba % DA;
    int ai = a / 7, aj = a % 7;
    int c = threadIdx.x;              // 512
    float s = 0.f;
#pragma unroll
    for (int di = 0; di < 4; di++)
#pragma unroll
        for (int dj = 0; dj < 4; dj++)
            s += g_q[((size_t)(b * NTOK + (ai * 4 + di) * WW + (aj * 4 + dj))) * DIM + c];
    g_agent[(size_t)ba * DIM + c] = s * 0.0625f;
}

// ======================= bias precompute =======================
__device__ __forceinline__ float bilin7(const float* __restrict__ t, int i, int j)
{
    float si = (i - 1.5f) * 0.25f;
    float sj = (j - 1.5f) * 0.25f;
    float fi = floorf(si), fj = floorf(sj);
    int i0 = (int)fi, j0 = (int)fj;
    float wi = si - fi, wj = sj - fj;
    int i0c = max(0, min(6, i0)), i1c = max(0, min(6, i0 + 1));
    int j0c = max(0, min(6, j0)), j1c = max(0, min(6, j0 + 1));
    float v00 = t[i0c * 7 + j0c], v01 = t[i0c * 7 + j1c];
    float v10 = t[i1c * 7 + j0c], v11 = t[i1c * 7 + j1c];
    return (1.f - wi) * ((1.f - wj) * v00 + wj * v01)
         +        wi  * ((1.f - wj) * v10 + wj * v11);
}

__global__ void build_bias(const float* __restrict__ an_bias, const float* __restrict__ na_bias,
                           const float* __restrict__ ah_bias, const float* __restrict__ aw_bias,
                           const float* __restrict__ ha_bias, const float* __restrict__ wa_bias)
{
    int ha = blockIdx.x;              // h*49 + a
    int h = ha / DA, a = ha % DA;
    int n = threadIdx.x;              // 784
    int i = n / WW, j = n % WW;
    g_pos_bias[(size_t)ha * NTOK + n] =
        bilin7(an_bias + (size_t)ha * 49, i, j) + ah_bias[ha * HH + i] + aw_bias[ha * WW + j];
    g_agent_bias[((size_t)h * NTOK + n) * DA + a] =
        bilin7(na_bias + (size_t)ha * 49, i, j)
        + ha_bias[(h * HH + i) * DA + a] + wa_bias[(h * WW + j) * DA + a];
}

// ======================= agent attention (batched: one block per (b,h)) =======================
// dyn smem: S[49][784] + A[49][64]
#define AA_SMEM_BYTES ((DA * NTOK + DA * HD) * 4)

__global__ void agent_attn()
{
    extern __shared__ float sm[];
    float* sS = sm;                  // [49][784]
    float* sA = sm + DA * NTOK;      // [49][64]
    __shared__ float sInv[52];
    int h = blockIdx.x, b = blockIdx.y;
    int tid = threadIdx.x;

    for (int i = tid; i < DA * HD; i += 256) {
        int a = i >> 6, d = i & 63;
        sA[i] = g_agent[((size_t)(b * DA + a)) * DIM + h * HD + d] * 0.125f;
    }
    __syncthreads();

    // scores: S[a][n] = sA[a].k[n] + pos_bias[h][a][n]
    for (int n = tid; n < NTOK; n += 256) {
        float kreg[HD];
        const float4* kr = (const float4*)(g_kv + ((size_t)(b * NTOK + n)) * (2 * DIM) + h * HD);
#pragma unroll
        for (int d4 = 0; d4 < 16; d4++) {
            float4 k4 = kr[d4];
            kreg[d4 * 4 + 0] = k4.x; kreg[d4 * 4 + 1] = k4.y;
            kreg[d4 * 4 + 2] = k4.z; kreg[d4 * 4 + 3] = k4.w;
        }
        const float* pb = g_pos_bias + (size_t)h * DA * NTOK + n;
        for (int a = 0; a < DA; a++) {
            const float4* Ar = (const float4*)&sA[a * HD];
            float s = 0.f;
#pragma unroll
            for (int d4 = 0; d4 < 16; d4++) {
                float4 a4 = Ar[d4];
                s = fmaf(kreg[d4 * 4 + 0], a4.x, s);
                s = fmaf(kreg[d4 * 4 + 1], a4.y, s);
                s = fmaf(kreg[d4 * 4 + 2], a4.z, s);
                s = fmaf(kreg[d4 * 4 + 3], a4.w, s);
            }
            sS[a * NTOK + n] = s + pb[a * NTOK];
        }
    }
    __syncthreads();

    // row softmax (warp per agent row)
    int warp = tid >> 5, lane = tid & 31;
    for (int a = warp; a < DA; a += 8) {
        float* row = sS + a * NTOK;
        float m = -1e30f;
        for (int n = lane; n < NTOK; n += 32) m = fmaxf(m, row[n]);
#pragma unroll
        for (int o = 16; o > 0; o >>= 1) m = fmaxf(m, __shfl_xor_sync(0xffffffff, m, o));
        float s = 0.f;
        for (int n = lane; n < NTOK; n += 32) { float e = __expf(row[n] - m); row[n] = e; s += e; }
#pragma unroll
        for (int o = 16; o > 0; o >>= 1) s += __shfl_xor_sync(0xffffffff, s, o);
        if (lane == 0) sInv[a] = 1.f / s;
    }
    __syncthreads();

    // AV: agent_v[a][d] = sum_n P[a][n] * v[n][d]; 4 d-groups, reg accumulators
    int d = tid & 63, grp = tid >> 6;    // grp owns a = grp, grp+4, ...
    float acc[13];
#pragma unroll
    for (int i = 0; i < 13; i++) acc[i] = 0.f;
    const float* vbase = g_kv + (size_t)b * NTOK * (2 * DIM) + DIM + h * HD + d;
    for (int n = 0; n < NTOK; n++) {
        float v = vbase[(size_t)n * (2 * DIM)];
        int a = grp;
#pragma unroll
        for (int i = 0; i < 13; i++) {
            if (a < DA) acc[i] = fmaf(sS[a * NTOK + n], v, acc[i]);
            a += 4;
        }
    }
    {
        int a = grp;
#pragma unroll
        for (int i = 0; i < 13; i++) {
            if (a < DA)
                g_agent_v[(((size_t)(b * NH + h)) * DA + a) * HD + d] = acc[i] * sInv[a];
            a += 4;
        }
    }
}

// ======================= q attention =======================
__global__ void q_attn()
{
    int h = blockIdx.x, b = blockIdx.y;
    __shared__ float sA [DA * HD];
    __shared__ float sAV[DA * HD];
    int tid = threadIdx.x;
    for (int i = tid; i < DA * HD; i += 256) {
        int a = i >> 6, d = i & 63;
        sA [i] = g_agent[((size_t)(b * DA + a)) * DIM + h * HD + d];
        sAV[i] = g_agent_v[(((size_t)(b * NH + h)) * DA + a) * HD + d];
    }
    __syncthreads();

    for (int n = tid; n < NTOK; n += 256) {
        float qr[HD];
        const float4* qp = (const float4*)(g_q + ((size_t)(b * NTOK + n)) * DIM + h * HD);
#pragma unroll
        for (int d4 = 0; d4 < 16; d4++) {
            float4 v4 = qp[d4];
            qr[d4 * 4 + 0] = v4.x * 0.125f; qr[d4 * 4 + 1] = v4.y * 0.125f;
            qr[d4 * 4 + 2] = v4.z * 0.125f; qr[d4 * 4 + 3] = v4.w * 0.125f;
        }
        const float* ab = g_agent_bias + ((size_t)(h * NTOK + n)) * DA;
        float sc[DA];
        float m = -1e30f;
        for (int a = 0; a < DA; a++) {
            float s = ab[a];
            const float* Ar = &sA[a * HD];
#pragma unroll
            for (int d = 0; d < HD; d++) s = fmaf(qr[d], Ar[d], s);
            sc[a] = s; m = fmaxf(m, s);
        }
        float sum = 0.f;
        for (int a = 0; a < DA; a++) { float e = __expf(sc[a] - m); sc[a] = e; sum += e; }
        float inv = 1.f / sum;

        float o[HD];
#pragma unroll
        for (int d = 0; d < HD; d++) o[d] = 0.f;
        for (int a = 0; a < DA; a++) {
            float p = sc[a] * inv;
            const float* Vr = &sAV[a * HD];
#pragma unroll
            for (int d = 0; d < HD; d++) o[d] = fmaf(p, Vr[d], o[d]);
        }
        float* op = g_attn + ((size_t)(b * NTOK + n)) * DIM + h * HD;
#pragma unroll
        for (int d4 = 0; d4 < 16; d4++) {
            float4 v4;
            v4.x = o[d4 * 4 + 0]; v4.y = o[d4 * 4 + 1];
            v4.z = o[d4 * 4 + 2]; v4.w = o[d4 * 4 + 3];
            ((float4*)op)[d4] = v4;
        }
    }
}

// ======================= depthwise 3x3 conv on v, + attn, -> tf32 =======================
__global__ void dwc_add(const float* __restrict__ w, const float* __restrict__ bias)
{
    int n = blockIdx.x, b = blockIdx.y;
    int c = threadIdx.x;              // 512
    int i = n / WW, j = n % WW;
    float acc = bias[c];
#pragma unroll
    for (int di = 0; di < 3; di++) {
        int ii = i + di - 1;
        if (ii < 0 || ii > HH - 1) continue;
#pragma unroll
        for (int dj = 0; dj < 3; dj++) {
            int jj = j + dj - 1;
            if (jj < 0 || jj > WW - 1) continue;
            acc = fmaf(w[c * 9 + di * 3 + dj],
                       g_kv[((size_t)(b * NTOK + ii * WW + jj)) * (2 * DIM) + DIM + c], acc);
        }
    }
    size_t idx = ((size_t)(b * NTOK + n)) * DIM + c;
    g_attn_t[idx] = f2tf(g_attn[idx] + acc);
}

// ======================= launch =======================
extern "C" void kernel_launch(void* const* d_in, const int* in_sizes, int n_in,
                              void* d_out, int out_size)
{
    const float* x       = (const float*)d_in[0];
    const float* q_w     = (const float*)d_in[1];
    const float* kv_w    = (const float*)d_in[2];
    const float* proj_w  = (const float*)d_in[3];
    const float* proj_b  = (const float*)d_in[4];
    const float* dwc_w   = (const float*)d_in[5];
    const float* dwc_b   = (const float*)d_in[6];
    const float* an_bias = (const float*)d_in[7];
    const float* na_bias = (const float*)d_in[8];
    const float* ah_bias = (const float*)d_in[9];
    const float* aw_bias = (const float*)d_in[10];
    const float* ha_bias = (const float*)d_in[11];
    const float* wa_bias = (const float*)d_in[12];
    float* out = (float*)d_out;

    cudaFuncSetAttribute(gemm_q,    cudaFuncAttributeMaxDynamicSharedMemorySize, GEMM_SMEM_BYTES);
    cudaFuncSetAttribute(gemm_kv,   cudaFuncAttributeMaxDynamicSharedMemorySize, GEMM_SMEM_BYTES);
    cudaFuncSetAttribute(gemm_proj, cudaFuncAttributeMaxDynamicSharedMemorySize, GEMM_SMEM_BYTES);
    cudaFuncSetAttribute(agent_attn, cudaFuncAttributeMaxDynamicSharedMemorySize, AA_SMEM_BYTES);

    // resolve device-global scratch addresses (host side)
    uint32_t *p_xt, *p_qw, *p_kvw, *p_pw;
    cudaGetSymbolAddress((void**)&p_xt,  g_xt);
    cudaGetSymbolAddress((void**)&p_qw,  g_qw_t);
    cudaGetSymbolAddress((void**)&p_kvw, g_kvw_t);
    cudaGetSymbolAddress((void**)&p_pw,  g_pw_t);

    // convert inputs to tf32
    cvt_tf32_kernel<<<(BATCH * NTOK * DIM / 4 + 255) / 256, 256>>>((const float4*)x, (uint4*)p_xt, BATCH * NTOK * DIM / 4);
    cvt_tf32_kernel<<<(DIM * DIM / 4 + 255) / 256, 256>>>((const float4*)q_w, (uint4*)p_qw, DIM * DIM / 4);
    cvt_tf32_kernel<<<(2 * DIM * DIM / 4 + 255) / 256, 256>>>((const float4*)kv_w, (uint4*)p_kvw, 2 * DIM * DIM / 4);
    cvt_tf32_kernel<<<(DIM * DIM / 4 + 255) / 256, 256>>>((const float4*)proj_w, (uint4*)p_pw, DIM * DIM / 4);

    gemm_q <<<dim3(DIM / 128, (BATCH * NTOK) / 128), 256, GEMM_SMEM_BYTES>>>();
    gemm_kv<<<dim3((2 * DIM) / 128, (BATCH * NTOK) / 128), 256, GEMM_SMEM_BYTES>>>();
    pool_agent<<<BATCH * DA, DIM>>>();
    build_bias<<<NH * DA, NTOK>>>(an_bias, na_bias, ah_bias, aw_bias, ha_bias, wa_bias);
    agent_attn<<<dim3(NH, BATCH), 256, AA_SMEM_BYTES>>>();
    q_attn<<<dim3(NH, BATCH), 256>>>();
    dwc_add<<<dim3(NTOK, BATCH), DIM>>>(dwc_w, dwc_b);
    gemm_proj<<<dim3(DIM / 128, (BATCH * NTOK) / 128), 256, GEMM_SMEM_BYTES>>>(proj_b, out);
}

// round 4
// speedup vs baseline: 1.0123x; 1.0123x over previous
#include <cuda_runtime.h>
#include <math.h>
#include <stdint.h>

// Problem constants
#define BATCH 32
#define NTOK  784
#define DIM   512
#define NH    8
#define HD    64
#define HH    28
#define WW    28
#define DA    49

// -------- scratch (__device__ globals; no allocations allowed) --------
__device__ float    g_q    [BATCH * NTOK * DIM];
__device__ float    g_kv   [BATCH * NTOK * 2 * DIM];   // k at +0, v at +512 within 1024-stride row
__device__ float    g_agent[BATCH * DA * DIM];
__device__ float    g_agent_v[BATCH * NH * DA * HD];
__device__ float    g_pos_bias[NH * DA * NTOK];        // [h,a,n]
__device__ float    g_agent_bias[NH * NTOK * DA];      // [h,n,a]
__device__ float    g_attn [BATCH * NTOK * DIM];       // float attn staging (pre-dwc)
// tf32 (pre-converted) operands for tensor-core GEMMs
__device__ uint32_t g_xt   [BATCH * NTOK * DIM];
__device__ uint32_t g_qkvw_t[3 * DIM * DIM];           // q_w then kv_w, concatenated row-major [1536][512]
__device__ uint32_t g_pw_t [DIM * DIM];
__device__ uint32_t g_attn_t[BATCH * NTOK * DIM];

__device__ __forceinline__ uint32_t f2tf(float f) {
    uint32_t u;
    asm("cvt.rna.tf32.f32 %0, %1;" : "=r"(u) : "f"(f));
    return u;
}

// ======================= fp32 -> tf32 conversion =======================
__global__ void cvt_x_kernel(const float4* __restrict__ in, uint4* __restrict__ out, int n4)
{
    int i = blockIdx.x * blockDim.x + threadIdx.x;
    if (i < n4) {
        float4 v = in[i];
        uint4 o;
        o.x = f2tf(v.x); o.y = f2tf(v.y); o.z = f2tf(v.z); o.w = f2tf(v.w);
        out[i] = o;
    }
}

// weights: y=0 -> q_w (into g_qkvw_t[0:256K]), y=1 -> kv_w (into +256K), y=2 -> proj_w (g_pw_t)
__global__ void cvt_w_kernel(const float* __restrict__ q_w, const float* __restrict__ kv_w,
                             const float* __restrict__ proj_w)
{
    int seg = blockIdx.y;
    const float4* src;
    uint4* dst;
    int n4;
    if (seg == 0)      { src = (const float4*)q_w;    dst = (uint4*)g_qkvw_t;                 n4 = DIM * DIM / 4; }
    else if (seg == 1) { src = (const float4*)kv_w;   dst = (uint4*)(g_qkvw_t + DIM * DIM);   n4 = 2 * DIM * DIM / 4; }
    else               { src = (const float4*)proj_w; dst = (uint4*)g_pw_t;                   n4 = DIM * DIM / 4; }
    for (int i = blockIdx.x * blockDim.x + threadIdx.x; i < n4; i += gridDim.x * blockDim.x) {
        float4 v = src[i];
        uint4 o;
        o.x = f2tf(v.x); o.y = f2tf(v.y); o.z = f2tf(v.z); o.w = f2tf(v.w);
        dst[i] = o;
    }
}

// ======================= TF32 tensor-core GEMM, cp.async 4-stage =======================
#define GSTAGES 4
#define STAGE_ELEMS (2 * 128 * 20)
#define GEMM_SMEM_BYTES (GSTAGES * STAGE_ELEMS * 4)   // 81920

__device__ __forceinline__ void cp_async16(uint32_t saddr, const void* gptr) {
    asm volatile("cp.async.ca.shared.global [%0], [%1], 16;" :: "r"(saddr), "l"(gptr));
}
__device__ __forceinline__ void cp_commit() {
    asm volatile("cp.async.commit_group;");
}
template<int N> __device__ __forceinline__ void cp_wait() {
    asm volatile("cp.async.wait_group %0;" :: "n"(N));
}

__device__ __forceinline__ void mma_tf32(float* d, const uint32_t* a, const uint32_t* b) {
    asm volatile(
        "mma.sync.aligned.m16n8k8.row.col.f32.tf32.tf32.f32 "
        "{%0,%1,%2,%3}, {%4,%5,%6,%7}, {%8,%9}, {%0,%1,%2,%3};"
        : "+f"(d[0]), "+f"(d[1]), "+f"(d[2]), "+f"(d[3])
        : "r"(a[0]), "r"(a[1]), "r"(a[2]), "r"(a[3]), "r"(b[0]), "r"(b[1]));
}

// computes the 128x128 tile accumulators; caller does the epilogue
__device__ __forceinline__ void tf32_gemm_main(const uint32_t* __restrict__ A,
                                               const uint32_t* __restrict__ W,
                                               int K, float acc[4][4][4])
{
    extern __shared__ uint32_t dsm[];
    const int row0 = blockIdx.y * 128;
    const int col0 = blockIdx.x * 128;
    const int tid  = threadIdx.x;
    const int lane = tid & 31;
    const int warp = tid >> 5;
    const int wm = warp >> 2;
    const int wn = warp & 3;
    const int gid = lane >> 2;
    const int tig = lane & 3;

    const int lr = tid >> 1;
    const int lc = (tid & 1) * 8;

    const uint32_t* Ag = A + (size_t)(row0 + lr) * K + lc;
    const uint32_t* Wg = W + (size_t)(col0 + lr) * K + lc;

    uint32_t smem_base = (uint32_t)__cvta_generic_to_shared(dsm);
    const uint32_t a_dst = smem_base + (uint32_t)(lr * 20 + lc) * 4;
    const uint32_t b_dst = a_dst + 128 * 20 * 4;

    const int NITER = K >> 4;

#pragma unroll
    for (int i = 0; i < 4; i++)
#pragma unroll
        for (int j = 0; j < 4; j++)
#pragma unroll
            for (int r = 0; r < 4; r++) acc[i][j][r] = 0.f;

#pragma unroll
    for (int s = 0; s < GSTAGES - 1; s++) {
        uint32_t so = (uint32_t)(s * STAGE_ELEMS) * 4;
        cp_async16(a_dst + so,      Ag + s * 16);
        cp_async16(a_dst + so + 16, Ag + s * 16 + 4);
        cp_async16(b_dst + so,      Wg + s * 16);
        cp_async16(b_dst + so + 16, Wg + s * 16 + 4);
        cp_commit();
    }

    for (int it = 0; it < NITER; it++) {
        cp_wait<GSTAGES - 2>();
        __syncthreads();

        int nxt = it + GSTAGES - 1;
        if (nxt < NITER) {
            int s = nxt & (GSTAGES - 1);
            uint32_t so = (uint32_t)(s * STAGE_ELEMS) * 4;
            cp_async16(a_dst + so,      Ag + nxt * 16);
            cp_async16(a_dst + so + 16, Ag + nxt * 16 + 4);
            cp_async16(b_dst + so,      Wg + nxt * 16);
            cp_async16(b_dst + so + 16, Wg + nxt * 16 + 4);
        }
        cp_commit();

        const uint32_t* As = dsm + (it & (GSTAGES - 1)) * STAGE_ELEMS;
        const uint32_t* Bs = As + 128 * 20;

#pragma unroll
        for (int kk = 0; kk < 16; kk += 8) {
            uint32_t af[4][4], bf[4][2];
#pragma unroll
            for (int mt = 0; mt < 4; mt++) {
                int r = wm * 64 + mt * 16 + gid;
                af[mt][0] = As[r * 20 + kk + tig];
                af[mt][1] = As[(r + 8) * 20 + kk + tig];
                af[mt][2] = As[r * 20 + kk + tig + 4];
                af[mt][3] = As[(r + 8) * 20 + kk + tig + 4];
            }
#pragma unroll
            for (int nt = 0; nt < 4; nt++) {
                int cb = wn * 32 + nt * 8 + gid;
                bf[nt][0] = Bs[cb * 20 + kk + tig];
                bf[nt][1] = Bs[cb * 20 + kk + tig + 4];
            }
#pragma unroll
            for (int mt = 0; mt < 4; mt++)
#pragma unroll
                for (int nt = 0; nt < 4; nt++)
                    mma_tf32(acc[mt][nt], af[mt], bf[nt]);
        }
    }
}

// merged QKV GEMM: A = g_xt [25088, 512], W = g_qkvw_t [1536, 512].
// cols 0..511 -> g_q (ldc 512); cols 512..1535 -> g_kv (ldc 1024)
__global__ void __launch_bounds__(256, 2) gemm_qkv()
{
    float acc[4][4][4];
    tf32_gemm_main(g_xt, g_qkvw_t, DIM, acc);

    const int row0 = blockIdx.y * 128;
    const int col0 = blockIdx.x * 128;
    const int tid  = threadIdx.x;
    const int lane = tid & 31;
    const int warp = tid >> 5;
    const int wm = warp >> 2, wn = warp & 3;
    const int gid = lane >> 2, tig = lane & 3;

    float* C;
    int ldc, cbase;
    if (col0 < DIM) { C = g_q;  ldc = DIM;     cbase = col0; }
    else            { C = g_kv; ldc = 2 * DIM; cbase = col0 - DIM; }

#pragma unroll
    for (int mt = 0; mt < 4; mt++) {
        int r = row0 + wm * 64 + mt * 16 + gid;
#pragma unroll
        for (int nt = 0; nt < 4; nt++) {
            int c = cbase + wn * 32 + nt * 8 + 2 * tig;
            *(float2*)&C[(size_t)r * ldc + c]       = make_float2(acc[mt][nt][0], acc[mt][nt][1]);
            *(float2*)&C[(size_t)(r + 8) * ldc + c] = make_float2(acc[mt][nt][2], acc[mt][nt][3]);
        }
    }
}

__global__ void __launch_bounds__(256, 2) gemm_proj(const float* __restrict__ bias,
                                                    float* __restrict__ out)
{
    float acc[4][4][4];
    tf32_gemm_main(g_attn_t, g_pw_t, DIM, acc);

    const int row0 = blockIdx.y * 128;
    const int col0 = blockIdx.x * 128;
    const int tid  = threadIdx.x;
    const int lane = tid & 31;
    const int warp = tid >> 5;
    const int wm = warp >> 2, wn = warp & 3;
    const int gid = lane >> 2, tig = lane & 3;

#pragma unroll
    for (int mt = 0; mt < 4; mt++) {
        int r = row0 + wm * 64 + mt * 16 + gid;
#pragma unroll
        for (int nt = 0; nt < 4; nt++) {
            int c = col0 + wn * 32 + nt * 8 + 2 * tig;
            float2 bb = *(const float2*)&bias[c];
            *(float2*)&out[(size_t)r * DIM + c] =
                make_float2(acc[mt][nt][0] + bb.x, acc[mt][nt][1] + bb.y);
            *(float2*)&out[(size_t)(r + 8) * DIM + c] =
                make_float2(acc[mt][nt][2] + bb.x, acc[mt][nt][3] + bb.y);
        }
    }
}

// ======================= agent = 4x4 avg pool of q image =======================
__global__ void pool_agent()
{
    int ba = blockIdx.x;
    int b = ba / DA, a = ba % DA;
    int ai = a / 7, aj = a % 7;
    int c = threadIdx.x;
    float s = 0.f;
#pragma unroll
    for (int di = 0; di < 4; di++)
#pragma unroll
        for (int dj = 0; dj < 4; dj++)
            s += g_q[((size_t)(b * NTOK + (ai * 4 + di) * WW + (aj * 4 + dj))) * DIM + c];
    g_agent[(size_t)ba * DIM + c] = s * 0.0625f;
}

// ======================= bias precompute =======================
__device__ __forceinline__ float bilin7(const float* __restrict__ t, int i, int j)
{
    float si = (i - 1.5f) * 0.25f;
    float sj = (j - 1.5f) * 0.25f;
    float fi = floorf(si), fj = floorf(sj);
    int i0 = (int)fi, j0 = (int)fj;
    float wi = si - fi, wj = sj - fj;
    int i0c = max(0, min(6, i0)), i1c = max(0, min(6, i0 + 1));
    int j0c = max(0, min(6, j0)), j1c = max(0, min(6, j0 + 1));
    float v00 = t[i0c * 7 + j0c], v01 = t[i0c * 7 + j1c];
    float v10 = t[i1c * 7 + j0c], v11 = t[i1c * 7 + j1c];
    return (1.f - wi) * ((1.f - wj) * v00 + wj * v01)
         +        wi  * ((1.f - wj) * v10 + wj * v11);
}

__global__ void build_bias(const float* __restrict__ an_bias, const float* __restrict__ na_bias,
                           const float* __restrict__ ah_bias, const float* __restrict__ aw_bias,
                           const float* __restrict__ ha_bias, const float* __restrict__ wa_bias)
{
    int ha = blockIdx.x;
    int h = ha / DA, a = ha % DA;
    int n = threadIdx.x;
    int i = n / WW, j = n % WW;
    g_pos_bias[(size_t)ha * NTOK + n] =
        bilin7(an_bias + (size_t)ha * 49, i, j) + ah_bias[ha * HH + i] + aw_bias[ha * WW + j];
    g_agent_bias[((size_t)h * NTOK + n) * DA + a] =
        bilin7(na_bias + (size_t)ha * 49, i, j)
        + ha_bias[(h * HH + i) * DA + a] + wa_bias[(h * WW + j) * DA + a];
}

// ======================= agent attention (one block per (b,h)) =======================
#define AA_SMEM_BYTES ((DA * NTOK + DA * HD) * 4)

__global__ void agent_attn()
{
    extern __shared__ float sm[];
    float* sS = sm;                  // [49][784]
    float* sA = sm + DA * NTOK;      // [49][64]
    __shared__ float sInv[52];
    int h = blockIdx.x, b = blockIdx.y;
    int tid = threadIdx.x;

    for (int i = tid; i < DA * HD; i += 256) {
        int a = i >> 6, d = i & 63;
        sA[i] = g_agent[((size_t)(b * DA + a)) * DIM + h * HD + d] * 0.125f;
    }
    __syncthreads();

    for (int n = tid; n < NTOK; n += 256) {
        float kreg[HD];
        const float4* kr = (const float4*)(g_kv + ((size_t)(b * NTOK + n)) * (2 * DIM) + h * HD);
#pragma unroll
        for (int d4 = 0; d4 < 16; d4++) {
            float4 k4 = kr[d4];
            kreg[d4 * 4 + 0] = k4.x; kreg[d4 * 4 + 1] = k4.y;
            kreg[d4 * 4 + 2] = k4.z; kreg[d4 * 4 + 3] = k4.w;
        }
        const float* pb = g_pos_bias + (size_t)h * DA * NTOK + n;
        for (int a = 0; a < DA; a++) {
            const float4* Ar = (const float4*)&sA[a * HD];
            float s = 0.f;
#pragma unroll
            for (int d4 = 0; d4 < 16; d4++) {
                float4 a4 = Ar[d4];
                s = fmaf(kreg[d4 * 4 + 0], a4.x, s);
                s = fmaf(kreg[d4 * 4 + 1], a4.y, s);
                s = fmaf(kreg[d4 * 4 + 2], a4.z, s);
                s = fmaf(kreg[d4 * 4 + 3], a4.w, s);
            }
            sS[a * NTOK + n] = s + pb[a * NTOK];
        }
    }
    __syncthreads();

    int warp = tid >> 5, lane = tid & 31;
    for (int a = warp; a < DA; a += 8) {
        float* row = sS + a * NTOK;
        float m = -1e30f;
        for (int n = lane; n < NTOK; n += 32) m = fmaxf(m, row[n]);
#pragma unroll
        for (int o = 16; o > 0; o >>= 1) m = fmaxf(m, __shfl_xor_sync(0xffffffff, m, o));
        float s = 0.f;
        for (int n = lane; n < NTOK; n += 32) { float e = __expf(row[n] - m); row[n] = e; s += e; }
#pragma unroll
        for (int o = 16; o > 0; o >>= 1) s += __shfl_xor_sync(0xffffffff, s, o);
        if (lane == 0) sInv[a] = 1.f / s;
    }
    __syncthreads();

    int d = tid & 63, grp = tid >> 6;
    float acc[13];
#pragma unroll
    for (int i = 0; i < 13; i++) acc[i] = 0.f;
    const float* vbase = g_kv + (size_t)b * NTOK * (2 * DIM) + DIM + h * HD + d;
    for (int n = 0; n < NTOK; n++) {
        float v = vbase[(size_t)n * (2 * DIM)];
        int a = grp;
#pragma unroll
        for (int i = 0; i < 13; i++) {
            if (a < DA) acc[i] = fmaf(sS[a * NTOK + n], v, acc[i]);
            a += 4;
        }
    }
    {
        int a = grp;
#pragma unroll
        for (int i = 0; i < 13; i++) {
            if (a < DA)
                g_agent_v[(((size_t)(b * NH + h)) * DA + a) * HD + d] = acc[i] * sInv[a];
            a += 4;
        }
    }
}

// ======================= q attention =======================
__global__ void q_attn()
{
    int h = blockIdx.x, b = blockIdx.y;
    __shared__ float sA [DA * HD];
    __shared__ float sAV[DA * HD];
    int tid = threadIdx.x;
    for (int i = tid; i < DA * HD; i += 256) {
        int a = i >> 6, d = i & 63;
        sA [i] = g_agent[((size_t)(b * DA + a)) * DIM + h * HD + d];
        sAV[i] = g_agent_v[(((size_t)(b * NH + h)) * DA + a) * HD + d];
    }
    __syncthreads();

    for (int n = tid; n < NTOK; n += 256) {
        float qr[HD];
        const float4* qp = (const float4*)(g_q + ((size_t)(b * NTOK + n)) * DIM + h * HD);
#pragma unroll
        for (int d4 = 0; d4 < 16; d4++) {
            float4 v4 = qp[d4];
            qr[d4 * 4 + 0] = v4.x * 0.125f; qr[d4 * 4 + 1] = v4.y * 0.125f;
            qr[d4 * 4 + 2] = v4.z * 0.125f; qr[d4 * 4 + 3] = v4.w * 0.125f;
        }
        const float* ab = g_agent_bias + ((size_t)(h * NTOK + n)) * DA;
        float sc[DA];
        float m = -1e30f;
        for (int a = 0; a < DA; a++) {
            float s = ab[a];
            const float* Ar = &sA[a * HD];
#pragma unroll
            for (int d = 0; d < HD; d++) s = fmaf(qr[d], Ar[d], s);
            sc[a] = s; m = fmaxf(m, s);
        }
        float sum = 0.f;
        for (int a = 0; a < DA; a++) { float e = __expf(sc[a] - m); sc[a] = e; sum += e; }
        float inv = 1.f / sum;

        float o[HD];
#pragma unroll
        for (int d = 0; d < HD; d++) o[d] = 0.f;
        for (int a = 0; a < DA; a++) {
            float p = sc[a] * inv;
            const float* Vr = &sAV[a * HD];
#pragma unroll
            for (int d = 0; d < HD; d++) o[d] = fmaf(p, Vr[d], o[d]);
        }
        float* op = g_attn + ((size_t)(b * NTOK + n)) * DIM + h * HD;
#pragma unroll
        for (int d4 = 0; d4 < 16; d4++) {
            float4 v4;
            v4.x = o[d4 * 4 + 0]; v4.y = o[d4 * 4 + 1];
            v4.z = o[d4 * 4 + 2]; v4.w = o[d4 * 4 + 3];
            ((float4*)op)[d4] = v4;
        }
    }
}

// ======================= depthwise 3x3 conv on v, + attn, -> tf32 =======================
__global__ void dwc_add(const float* __restrict__ w, const float* __restrict__ bias)
{
    int n = blockIdx.x, b = blockIdx.y;
    int c = threadIdx.x;
    int i = n / WW, j = n % WW;
    float acc = bias[c];
#pragma unroll
    for (int di = 0; di < 3; di++) {
        int ii = i + di - 1;
        if (ii < 0 || ii > HH - 1) continue;
#pragma unroll
        for (int dj = 0; dj < 3; dj++) {
            int jj = j + dj - 1;
            if (jj < 0 || jj > WW - 1) continue;
            acc = fmaf(w[c * 9 + di * 3 + dj],
                       g_kv[((size_t)(b * NTOK + ii * WW + jj)) * (2 * DIM) + DIM + c], acc);
        }
    }
    size_t idx = ((size_t)(b * NTOK + n)) * DIM + c;
    g_attn_t[idx] = f2tf(g_attn[idx] + acc);
}

// ======================= launch =======================
extern "C" void kernel_launch(void* const* d_in, const int* in_sizes, int n_in,
                              void* d_out, int out_size)
{
    const float* x       = (const float*)d_in[0];
    const float* q_w     = (const float*)d_in[1];
    const float* kv_w    = (const float*)d_in[2];
    const float* proj_w  = (const float*)d_in[3];
    const float* proj_b  = (const float*)d_in[4];
    const float* dwc_w   = (const float*)d_in[5];
    const float* dwc_b   = (const float*)d_in[6];
    const float* an_bias = (const float*)d_in[7];
    const float* na_bias = (const float*)d_in[8];
    const float* ah_bias = (const float*)d_in[9];
    const float* aw_bias = (const float*)d_in[10];
    const float* ha_bias = (const float*)d_in[11];
    const float* wa_bias = (const float*)d_in[12];
    float* out = (float*)d_out;

    cudaFuncSetAttribute(gemm_qkv,  cudaFuncAttributeMaxDynamicSharedMemorySize, GEMM_SMEM_BYTES);
    cudaFuncSetAttribute(gemm_proj, cudaFuncAttributeMaxDynamicSharedMemorySize, GEMM_SMEM_BYTES);
    cudaFuncSetAttribute(agent_attn, cudaFuncAttributeMaxDynamicSharedMemorySize, AA_SMEM_BYTES);

    uint32_t* p_xt;
    cudaGetSymbolAddress((void**)&p_xt, g_xt);

    // 1: convert x
    cvt_x_kernel<<<(BATCH * NTOK * DIM / 4 + 255) / 256, 256>>>((const float4*)x, (uint4*)p_xt,
                                                                 BATCH * NTOK * DIM / 4);
    // 2: convert weights
    cvt_w_kernel<<<dim3(128, 3), 256>>>(q_w, kv_w, proj_w);
    // 3: bias tables (independent)
    build_bias<<<NH * DA, NTOK>>>(an_bias, na_bias, ah_bias, aw_bias, ha_bias, wa_bias);
    // 4: merged QKV GEMM  <-- ncu-profiled slot
    gemm_qkv<<<dim3(3 * DIM / 128, (BATCH * NTOK) / 128), 256, GEMM_SMEM_BYTES>>>();
    // 5..: rest of the pipeline
    pool_agent<<<BATCH * DA, DIM>>>();
    agent_attn<<<dim3(NH, BATCH), 256, AA_SMEM_BYTES>>>();
    q_attn<<<dim3(NH, BATCH), 256>>>();
    dwc_add<<<dim3(NTOK, BATCH), DIM>>>(dwc_w, dwc_b);
    gemm_proj<<<dim3(DIM / 128, (BATCH * NTOK) / 128), 256, GEMM_SMEM_BYTES>>>(proj_b, out);
}

// round 5
// speedup vs baseline: 1.0709x; 1.0579x over previous
#include <cuda_runtime.h>
#include <math.h>
#include <stdint.h>

// Problem constants
#define BATCH 32
#define NTOK  784
#define DIM   512
#define NH    8
#define HD    64
#define HH    28
#define WW    28
#define DA    49

typedef unsigned long long u64;

// -------- scratch (__device__ globals; no allocations allowed) --------
__device__ float    g_q    [BATCH * NTOK * DIM];
__device__ float    g_kv   [BATCH * NTOK * 2 * DIM];   // k at +0, v at +512 within 1024-stride row
__device__ float    g_agent[BATCH * DA * DIM];
__device__ float    g_agent_v[BATCH * NH * DA * HD];
__device__ float    g_pos_bias[NH * DA * NTOK];        // [h,a,n]
__device__ float    g_agent_bias_t[NH * DA * NTOK];    // [h,a,n]  (transposed for coalesced reads)
__device__ float    g_attn [BATCH * NTOK * DIM];       // float attn staging (pre-dwc)
// tf32 (pre-converted) operands for tensor-core GEMMs
__device__ uint32_t g_xt   [BATCH * NTOK * DIM];
__device__ uint32_t g_qkvw_t[3 * DIM * DIM];           // q_w then kv_w [1536][512]
__device__ uint32_t g_pw_t [DIM * DIM];
__device__ uint32_t g_attn_t[BATCH * NTOK * DIM];

__device__ __forceinline__ uint32_t f2tf(float f) {
    uint32_t u;
    asm("cvt.rna.tf32.f32 %0, %1;" : "=r"(u) : "f"(f));
    return u;
}
__device__ __forceinline__ void fma2(u64& d, u64 a, u64 b) {
    asm("fma.rn.f32x2 %0, %1, %2, %0;" : "+l"(d) : "l"(a), "l"(b));
}
__device__ __forceinline__ float2 unpack2(u64 v) {
    float2 f;
    asm("mov.b64 {%0,%1}, %2;" : "=f"(f.x), "=f"(f.y) : "l"(v));
    return f;
}
__device__ __forceinline__ u64 pack2(float lo, float hi) {
    u64 r;
    asm("mov.b64 %0, {%1,%2};" : "=l"(r) : "f"(lo), "f"(hi));
    return r;
}

// ======================= fp32 -> tf32 conversion =======================
__global__ void cvt_x_kernel(const float4* __restrict__ in, uint4* __restrict__ out, int n4)
{
    int i = blockIdx.x * blockDim.x + threadIdx.x;
    if (i < n4) {
        float4 v = in[i];
        uint4 o;
        o.x = f2tf(v.x); o.y = f2tf(v.y); o.z = f2tf(v.z); o.w = f2tf(v.w);
        out[i] = o;
    }
}

__global__ void cvt_w_kernel(const float* __restrict__ q_w, const float* __restrict__ kv_w,
                             const float* __restrict__ proj_w)
{
    int seg = blockIdx.y;
    const float4* src;
    uint4* dst;
    int n4;
    if (seg == 0)      { src = (const float4*)q_w;    dst = (uint4*)g_qkvw_t;                 n4 = DIM * DIM / 4; }
    else if (seg == 1) { src = (const float4*)kv_w;   dst = (uint4*)(g_qkvw_t + DIM * DIM);   n4 = 2 * DIM * DIM / 4; }
    else               { src = (const float4*)proj_w; dst = (uint4*)g_pw_t;                   n4 = DIM * DIM / 4; }
    for (int i = blockIdx.x * blockDim.x + threadIdx.x; i < n4; i += gridDim.x * blockDim.x) {
        float4 v = src[i];
        uint4 o;
        o.x = f2tf(v.x); o.y = f2tf(v.y); o.z = f2tf(v.z); o.w = f2tf(v.w);
        dst[i] = o;
    }
}

// ======================= TF32 tensor-core GEMM, cp.async 4-stage =======================
#define GSTAGES 4
#define STAGE_ELEMS (2 * 128 * 20)
#define GEMM_SMEM_BYTES (GSTAGES * STAGE_ELEMS * 4)   // 81920

__device__ __forceinline__ void cp_async16(uint32_t saddr, const void* gptr) {
    asm volatile("cp.async.cg.shared.global [%0], [%1], 16;" :: "r"(saddr), "l"(gptr));
}
__device__ __forceinline__ void cp_commit() {
    asm volatile("cp.async.commit_group;");
}
template<int N> __device__ __forceinline__ void cp_wait() {
    asm volatile("cp.async.wait_group %0;" :: "n"(N));
}

__device__ __forceinline__ void mma_tf32(float* d, const uint32_t* a, const uint32_t* b) {
    asm volatile(
        "mma.sync.aligned.m16n8k8.row.col.f32.tf32.tf32.f32 "
        "{%0,%1,%2,%3}, {%4,%5,%6,%7}, {%8,%9}, {%0,%1,%2,%3};"
        : "+f"(d[0]), "+f"(d[1]), "+f"(d[2]), "+f"(d[3])
        : "r"(a[0]), "r"(a[1]), "r"(a[2]), "r"(a[3]), "r"(b[0]), "r"(b[1]));
}

__device__ __forceinline__ void tf32_gemm_main(const uint32_t* __restrict__ A,
                                               const uint32_t* __restrict__ W,
                                               int K, float acc[4][4][4])
{
    extern __shared__ uint32_t dsm[];
    const int row0 = blockIdx.y * 128;
    const int col0 = blockIdx.x * 128;
    const int tid  = threadIdx.x;
    const int lane = tid & 31;
    const int warp = tid >> 5;
    const int wm = warp >> 2;
    const int wn = warp & 3;
    const int gid = lane >> 2;
    const int tig = lane & 3;

    const int lr = tid >> 1;
    const int lc = (tid & 1) * 8;

    const uint32_t* Ag = A + (size_t)(row0 + lr) * K + lc;
    const uint32_t* Wg = W + (size_t)(col0 + lr) * K + lc;

    uint32_t smem_base = (uint32_t)__cvta_generic_to_shared(dsm);
    const uint32_t a_dst = smem_base + (uint32_t)(lr * 20 + lc) * 4;
    const uint32_t b_dst = a_dst + 128 * 20 * 4;

    const int NITER = K >> 4;

#pragma unroll
    for (int i = 0; i < 4; i++)
#pragma unroll
        for (int j = 0; j < 4; j++)
#pragma unroll
            for (int r = 0; r < 4; r++) acc[i][j][r] = 0.f;

#pragma unroll
    for (int s = 0; s < GSTAGES - 1; s++) {
        uint32_t so = (uint32_t)(s * STAGE_ELEMS) * 4;
        cp_async16(a_dst + so,      Ag + s * 16);
        cp_async16(a_dst + so + 16, Ag + s * 16 + 4);
        cp_async16(b_dst + so,      Wg + s * 16);
        cp_async16(b_dst + so + 16, Wg + s * 16 + 4);
        cp_commit();
    }

    for (int it = 0; it < NITER; it++) {
        cp_wait<GSTAGES - 2>();
        __syncthreads();

        int nxt = it + GSTAGES - 1;
        if (nxt < NITER) {
            int s = nxt & (GSTAGES - 1);
            uint32_t so = (uint32_t)(s * STAGE_ELEMS) * 4;
            cp_async16(a_dst + so,      Ag + nxt * 16);
            cp_async16(a_dst + so + 16, Ag + nxt * 16 + 4);
            cp_async16(b_dst + so,      Wg + nxt * 16);
            cp_async16(b_dst + so + 16, Wg + nxt * 16 + 4);
        }
        cp_commit();

        const uint32_t* As = dsm + (it & (GSTAGES - 1)) * STAGE_ELEMS;
        const uint32_t* Bs = As + 128 * 20;

#pragma unroll
        for (int kk = 0; kk < 16; kk += 8) {
            uint32_t af[4][4], bf[4][2];
#pragma unroll
            for (int mt = 0; mt < 4; mt++) {
                int r = wm * 64 + mt * 16 + gid;
                af[mt][0] = As[r * 20 + kk + tig];
                af[mt][1] = As[(r + 8) * 20 + kk + tig];
                af[mt][2] = As[r * 20 + kk + tig + 4];
                af[mt][3] = As[(r + 8) * 20 + kk + tig + 4];
            }
#pragma unroll
            for (int nt = 0; nt < 4; nt++) {
                int cb = wn * 32 + nt * 8 + gid;
                bf[nt][0] = Bs[cb * 20 + kk + tig];
                bf[nt][1] = Bs[cb * 20 + kk + tig + 4];
            }
#pragma unroll
            for (int mt = 0; mt < 4; mt++)
#pragma unroll
                for (int nt = 0; nt < 4; nt++)
                    mma_tf32(acc[mt][nt], af[mt], bf[nt]);
        }
    }
}

__global__ void __launch_bounds__(256, 2) gemm_qkv()
{
    float acc[4][4][4];
    tf32_gemm_main(g_xt, g_qkvw_t, DIM, acc);

    const int row0 = blockIdx.y * 128;
    const int col0 = blockIdx.x * 128;
    const int tid  = threadIdx.x;
    const int lane = tid & 31;
    const int warp = tid >> 5;
    const int wm = warp >> 2, wn = warp & 3;
    const int gid = lane >> 2, tig = lane & 3;

    float* C;
    int ldc, cbase;
    if (col0 < DIM) { C = g_q;  ldc = DIM;     cbase = col0; }
    else            { C = g_kv; ldc = 2 * DIM; cbase = col0 - DIM; }

#pragma unroll
    for (int mt = 0; mt < 4; mt++) {
        int r = row0 + wm * 64 + mt * 16 + gid;
#pragma unroll
        for (int nt = 0; nt < 4; nt++) {
            int c = cbase + wn * 32 + nt * 8 + 2 * tig;
            *(float2*)&C[(size_t)r * ldc + c]       = make_float2(acc[mt][nt][0], acc[mt][nt][1]);
            *(float2*)&C[(size_t)(r + 8) * ldc + c] = make_float2(acc[mt][nt][2], acc[mt][nt][3]);
        }
    }
}

__global__ void __launch_bounds__(256, 2) gemm_proj(const float* __restrict__ bias,
                                                    float* __restrict__ out)
{
    float acc[4][4][4];
    tf32_gemm_main(g_attn_t, g_pw_t, DIM, acc);

    const int row0 = blockIdx.y * 128;
    const int col0 = blockIdx.x * 128;
    const int tid  = threadIdx.x;
    const int lane = tid & 31;
    const int warp = tid >> 5;
    const int wm = warp >> 2, wn = warp & 3;
    const int gid = lane >> 2, tig = lane & 3;

#pragma unroll
    for (int mt = 0; mt < 4; mt++) {
        int r = row0 + wm * 64 + mt * 16 + gid;
#pragma unroll
        for (int nt = 0; nt < 4; nt++) {
            int c = col0 + wn * 32 + nt * 8 + 2 * tig;
            float2 bb = *(const float2*)&bias[c];
            *(float2*)&out[(size_t)r * DIM + c] =
                make_float2(acc[mt][nt][0] + bb.x, acc[mt][nt][1] + bb.y);
            *(float2*)&out[(size_t)(r + 8) * DIM + c] =
                make_float2(acc[mt][nt][2] + bb.x, acc[mt][nt][3] + bb.y);
        }
    }
}

// ======================= agent = 4x4 avg pool of q image =======================
__global__ void pool_agent()
{
    int ba = blockIdx.x;
    int b = ba / DA, a = ba % DA;
    int ai = a / 7, aj = a % 7;
    int c = threadIdx.x;
    float s = 0.f;
#pragma unroll
    for (int di = 0; di < 4; di++)
#pragma unroll
        for (int dj = 0; dj < 4; dj++)
            s += g_q[((size_t)(b * NTOK + (ai * 4 + di) * WW + (aj * 4 + dj))) * DIM + c];
    g_agent[(size_t)ba * DIM + c] = s * 0.0625f;
}

// ======================= bias precompute =======================
__device__ __forceinline__ float bilin7(const float* __restrict__ t, int i, int j)
{
    float si = (i - 1.5f) * 0.25f;
    float sj = (j - 1.5f) * 0.25f;
    float fi = floorf(si), fj = floorf(sj);
    int i0 = (int)fi, j0 = (int)fj;
    float wi = si - fi, wj = sj - fj;
    int i0c = max(0, min(6, i0)), i1c = max(0, min(6, i0 + 1));
    int j0c = max(0, min(6, j0)), j1c = max(0, min(6, j0 + 1));
    float v00 = t[i0c * 7 + j0c], v01 = t[i0c * 7 + j1c];
    float v10 = t[i1c * 7 + j0c], v11 = t[i1c * 7 + j1c];
    return (1.f - wi) * ((1.f - wj) * v00 + wj * v01)
         +        wi  * ((1.f - wj) * v10 + wj * v11);
}

__global__ void build_bias(const float* __restrict__ an_bias, const float* __restrict__ na_bias,
                           const float* __restrict__ ah_bias, const float* __restrict__ aw_bias,
                           const float* __restrict__ ha_bias, const float* __restrict__ wa_bias)
{
    int ha = blockIdx.x;
    int h = ha / DA, a = ha % DA;
    int n = threadIdx.x;
    int i = n / WW, j = n % WW;
    g_pos_bias[(size_t)ha * NTOK + n] =
        bilin7(an_bias + (size_t)ha * 49, i, j) + ah_bias[ha * HH + i] + aw_bias[ha * WW + j];
    // transposed agent bias: [h][a][n]
    g_agent_bias_t[(size_t)ha * NTOK + n] =
        bilin7(na_bias + (size_t)ha * 49, i, j)
        + ha_bias[(h * HH + i) * DA + a] + wa_bias[(h * WW + j) * DA + a];
}

// ======================= agent attention (one block per (b,h)) =======================
#define AA_SMEM_BYTES ((DA * NTOK + DA * HD) * 4)

__global__ void agent_attn()
{
    extern __shared__ float sm[];
    float* sS = sm;                  // [49][784]
    float* sA = sm + DA * NTOK;      // [49][64]
    __shared__ float sInv[52];
    int h = blockIdx.x, b = blockIdx.y;
    int tid = threadIdx.x;

    for (int i = tid; i < DA * HD; i += 256) {
        int a = i >> 6, d = i & 63;
        sA[i] = g_agent[((size_t)(b * DA + a)) * DIM + h * HD + d] * 0.125f;
    }
    __syncthreads();

    // scores: packed f32x2 dot products
    for (int n = tid; n < NTOK; n += 256) {
        u64 kp[32];
        const ulonglong2* kr = (const ulonglong2*)(g_kv + ((size_t)(b * NTOK + n)) * (2 * DIM) + h * HD);
#pragma unroll
        for (int i = 0; i < 16; i++) {
            ulonglong2 v = kr[i];
            kp[2 * i] = v.x; kp[2 * i + 1] = v.y;
        }
        const float* pb = g_pos_bias + (size_t)h * DA * NTOK + n;
        for (int a = 0; a < DA; a++) {
            const ulonglong2* Ar = (const ulonglong2*)&sA[a * HD];
            u64 acc0 = 0, acc1 = 0;
#pragma unroll
            for (int i = 0; i < 16; i++) {
                ulonglong2 av = Ar[i];
                fma2(acc0, kp[2 * i], av.x);
                fma2(acc1, kp[2 * i + 1], av.y);
            }
            float2 f0 = unpack2(acc0), f1 = unpack2(acc1);
            sS[a * NTOK + n] = (f0.x + f0.y) + (f1.x + f1.y) + pb[a * NTOK];
        }
    }
    __syncthreads();

    int warp = tid >> 5, lane = tid & 31;
    for (int a = warp; a < DA; a += 8) {
        float* row = sS + a * NTOK;
        float m = -1e30f;
        for (int n = lane; n < NTOK; n += 32) m = fmaxf(m, row[n]);
#pragma unroll
        for (int o = 16; o > 0; o >>= 1) m = fmaxf(m, __shfl_xor_sync(0xffffffff, m, o));
        float s = 0.f;
        for (int n = lane; n < NTOK; n += 32) { float e = __expf(row[n] - m); row[n] = e; s += e; }
#pragma unroll
        for (int o = 16; o > 0; o >>= 1) s += __shfl_xor_sync(0xffffffff, s, o);
        if (lane == 0) sInv[a] = 1.f / s;
    }
    __syncthreads();

    int d = tid & 63, grp = tid >> 6;
    float acc[13];
#pragma unroll
    for (int i = 0; i < 13; i++) acc[i] = 0.f;
    const float* vbase = g_kv + (size_t)b * NTOK * (2 * DIM) + DIM + h * HD + d;
    for (int n = 0; n < NTOK; n++) {
        float v = vbase[(size_t)n * (2 * DIM)];
        int a = grp;
#pragma unroll
        for (int i = 0; i < 13; i++) {
            if (a < DA) acc[i] = fmaf(sS[a * NTOK + n], v, acc[i]);
            a += 4;
        }
    }
    {
        int a = grp;
#pragma unroll
        for (int i = 0; i < 13; i++) {
            if (a < DA)
                g_agent_v[(((size_t)(b * NH + h)) * DA + a) * HD + d] = acc[i] * sInv[a];
            a += 4;
        }
    }
}

// ======================= q attention (spill-free, f32x2) =======================
// smem: sA[49][64] + sAV[49][64] + sS[256][51]
#define QA_SMEM_BYTES ((2 * DA * HD + 256 * 51) * 4)

__global__ void __launch_bounds__(256, 2) q_attn()
{
    extern __shared__ float qsm[];
    float* sA  = qsm;                    // [49][64]
    float* sAV = qsm + DA * HD;          // [49][64]
    float* sS  = qsm + 2 * DA * HD;      // [256][51]
    int h = blockIdx.x, b = blockIdx.y;
    int tid = threadIdx.x;

    for (int i = tid; i < DA * HD; i += 256) {
        int a = i >> 6, d = i & 63;
        sA [i] = g_agent[((size_t)(b * DA + a)) * DIM + h * HD + d] * 0.125f;
        sAV[i] = g_agent_v[(((size_t)(b * NH + h)) * DA + a) * HD + d];
    }
    __syncthreads();

    float* row = sS + tid * 51;
    for (int n = tid; n < NTOK; n += 256) {
        // phase 1: scores -> smem row
        u64 qp[32];
        const ulonglong2* qpt = (const ulonglong2*)(g_q + ((size_t)(b * NTOK + n)) * DIM + h * HD);
#pragma unroll
        for (int i = 0; i < 16; i++) {
            ulonglong2 v = qpt[i];
            qp[2 * i] = v.x; qp[2 * i + 1] = v.y;
        }
        const float* abT = g_agent_bias_t + (size_t)h * DA * NTOK + n;
        float m = -1e30f;
        for (int a = 0; a < DA; a++) {
            const ulonglong2* Ar = (const ulonglong2*)&sA[a * HD];
            u64 acc0 = 0, acc1 = 0;
#pragma unroll
            for (int i = 0; i < 16; i++) {
                ulonglong2 av = Ar[i];
                fma2(acc0, qp[2 * i], av.x);
                fma2(acc1, qp[2 * i + 1], av.y);
            }
            float2 f0 = unpack2(acc0), f1 = unpack2(acc1);
            float s = (f0.x + f0.y) + (f1.x + f1.y) + abT[a * NTOK];
            row[a] = s;
            m = fmaxf(m, s);
        }

        // softmax on smem row
        float sum = 0.f;
        for (int a = 0; a < DA; a++) { float e = __expf(row[a] - m); row[a] = e; sum += e; }
        float inv = 1.f / sum;

        // phase 2: O = P @ AV (packed accumulators; qp is dead here)
        u64 o[32];
#pragma unroll
        for (int i = 0; i < 32; i++) o[i] = 0;
        for (int a = 0; a < DA; a++) {
            float p = row[a] * inv;
            u64 pp = pack2(p, p);
            const ulonglong2* Vr = (const ulonglong2*)&sAV[a * HD];
#pragma unroll
            for (int i = 0; i < 16; i++) {
                ulonglong2 vv = Vr[i];
                fma2(o[2 * i], pp, vv.x);
                fma2(o[2 * i + 1], pp, vv.y);
            }
        }
        float4* op = (float4*)(g_attn + ((size_t)(b * NTOK + n)) * DIM + h * HD);
#pragma unroll
        for (int i = 0; i < 16; i++) {
            float2 lo = unpack2(o[2 * i]), hi = unpack2(o[2 * i + 1]);
            op[i] = make_float4(lo.x, lo.y, hi.x, hi.y);
        }
    }
}

// ======================= depthwise 3x3 conv on v, + attn, -> tf32 =======================
__global__ void dwc_add(const float* __restrict__ w, const float* __restrict__ bias)
{
    int n = blockIdx.x, b = blockIdx.y;
    int c = threadIdx.x;
    int i = n / WW, j = n % WW;
    float acc = bias[c];
#pragma unroll
    for (int di = 0; di < 3; di++) {
        int ii = i + di - 1;
        if (ii < 0 || ii > HH - 1) continue;
#pragma unroll
        for (int dj = 0; dj < 3; dj++) {
            int jj = j + dj - 1;
            if (jj < 0 || jj > WW - 1) continue;
            acc = fmaf(w[c * 9 + di * 3 + dj],
                       g_kv[((size_t)(b * NTOK + ii * WW + jj)) * (2 * DIM) + DIM + c], acc);
        }
    }
    size_t idx = ((size_t)(b * NTOK + n)) * DIM + c;
    g_attn_t[idx] = f2tf(g_attn[idx] + acc);
}

// ======================= launch =======================
extern "C" void kernel_launch(void* const* d_in, const int* in_sizes, int n_in,
                              void* d_out, int out_size)
{
    const float* x       = (const float*)d_in[0];
    const float* q_w     = (const float*)d_in[1];
    const float* kv_w    = (const float*)d_in[2];
    const float* proj_w  = (const float*)d_in[3];
    const float* proj_b  = (const float*)d_in[4];
    const float* dwc_w   = (const float*)d_in[5];
    const float* dwc_b   = (const float*)d_in[6];
    const float* an_bias = (const float*)d_in[7];
    const float* na_bias = (const float*)d_in[8];
    const float* ah_bias = (const float*)d_in[9];
    const float* aw_bias = (const float*)d_in[10];
    const float* ha_bias = (const float*)d_in[11];
    const float* wa_bias = (const float*)d_in[12];
    float* out = (float*)d_out;

    cudaFuncSetAttribute(gemm_qkv,   cudaFuncAttributeMaxDynamicSharedMemorySize, GEMM_SMEM_BYTES);
    cudaFuncSetAttribute(gemm_proj,  cudaFuncAttributeMaxDynamicSharedMemorySize, GEMM_SMEM_BYTES);
    cudaFuncSetAttribute(agent_attn, cudaFuncAttributeMaxDynamicSharedMemorySize, AA_SMEM_BYTES);
    cudaFuncSetAttribute(q_attn,     cudaFuncAttributeMaxDynamicSharedMemorySize, QA_SMEM_BYTES);

    uint32_t* p_xt;
    cudaGetSymbolAddress((void**)&p_xt, g_xt);

    // 1: convert x
    cvt_x_kernel<<<(BATCH * NTOK * DIM / 4 + 255) / 256, 256>>>((const float4*)x, (uint4*)p_xt,
                                                                 BATCH * NTOK * DIM / 4);
    // 2: convert weights
    cvt_w_kernel<<<dim3(128, 3), 256>>>(q_w, kv_w, proj_w);
    // 3: bias tables
    build_bias<<<NH * DA, NTOK>>>(an_bias, na_bias, ah_bias, aw_bias, ha_bias, wa_bias);
    // 4: merged QKV GEMM  <-- ncu-profiled slot
    gemm_qkv<<<dim3(3 * DIM / 128, (BATCH * NTOK) / 128), 256, GEMM_SMEM_BYTES>>>();
    // 5..: rest
    pool_agent<<<BATCH * DA, DIM>>>();
    agent_attn<<<dim3(NH, BATCH), 256, AA_SMEM_BYTES>>>();
    q_attn<<<dim3(NH, BATCH), 256, QA_SMEM_BYTES>>>();
    dwc_add<<<dim3(NTOK, BATCH), DIM>>>(dwc_w, dwc_b);
    gemm_proj<<<dim3(DIM / 128, (BATCH * NTOK) / 128), 256, GEMM_SMEM_BYTES>>>(proj_b, out);
}

// round 6
// speedup vs baseline: 1.5859x; 1.4809x over previous
#include <cuda_runtime.h>
#include <math.h>
#include <stdint.h>

// Problem constants
#define BATCH 32
#define NTOK  784
#define DIM   512
#define NH    8
#define HD    64
#define HH    28
#define WW    28
#define DA    49

typedef unsigned long long u64;

// -------- scratch (__device__ globals; no allocations allowed) --------
__device__ float    g_q    [BATCH * NTOK * DIM];
__device__ float    g_kv   [BATCH * NTOK * 2 * DIM];   // k at +0, v at +512 within 1024-stride row
__device__ float    g_pos_bias[NH * DA * NTOK];        // [h,a,n]
__device__ float    g_agent_bias_t[NH * DA * NTOK];    // [h,a,n]
__device__ float    g_attn [BATCH * NTOK * DIM];       // float attn staging (pre-dwc)
__device__ uint32_t g_xt   [BATCH * NTOK * DIM];
__device__ uint32_t g_qkvw_t[3 * DIM * DIM];           // q_w then kv_w [1536][512]
__device__ uint32_t g_pw_t [DIM * DIM];
__device__ uint32_t g_attn_t[BATCH * NTOK * DIM];

__device__ __forceinline__ uint32_t f2tf(float f) {
    uint32_t u;
    asm("cvt.rna.tf32.f32 %0, %1;" : "=r"(u) : "f"(f));
    return u;
}
__device__ __forceinline__ void fma2(u64& d, u64 a, u64 b) {
    asm("fma.rn.f32x2 %0, %1, %2, %0;" : "+l"(d) : "l"(a), "l"(b));
}
__device__ __forceinline__ float2 unpack2(u64 v) {
    float2 f;
    asm("mov.b64 {%0,%1}, %2;" : "=f"(f.x), "=f"(f.y) : "l"(v));
    return f;
}
__device__ __forceinline__ u64 pack2(float lo, float hi) {
    u64 r;
    asm("mov.b64 %0, {%1,%2};" : "=l"(r) : "f"(lo), "f"(hi));
    return r;
}

// ======================= fp32 -> tf32 conversion (all operands, one kernel) =======================
__global__ void cvt_all(const float4* __restrict__ x, const float4* __restrict__ qw,
                        const float4* __restrict__ kvw, const float4* __restrict__ pw)
{
    const float4* src;
    uint4* dst;
    int n4;
    switch (blockIdx.y) {
        case 0: src = x;   dst = (uint4*)g_xt;                 n4 = BATCH * NTOK * DIM / 4; break;
        case 1: src = qw;  dst = (uint4*)g_qkvw_t;             n4 = DIM * DIM / 4;          break;
        case 2: src = kvw; dst = (uint4*)(g_qkvw_t + DIM*DIM); n4 = 2 * DIM * DIM / 4;      break;
        default: src = pw; dst = (uint4*)g_pw_t;               n4 = DIM * DIM / 4;          break;
    }
    for (int i = blockIdx.x * blockDim.x + threadIdx.x; i < n4; i += gridDim.x * blockDim.x) {
        float4 v = src[i];
        uint4 o;
        o.x = f2tf(v.x); o.y = f2tf(v.y); o.z = f2tf(v.z); o.w = f2tf(v.w);
        dst[i] = o;
    }
}

// ======================= TF32 tensor-core GEMM, cp.async 4-stage =======================
#define GSTAGES 4
#define STAGE_ELEMS (2 * 128 * 20)
#define GEMM_SMEM_BYTES (GSTAGES * STAGE_ELEMS * 4)   // 81920

__device__ __forceinline__ void cp_async16(uint32_t saddr, const void* gptr) {
    asm volatile("cp.async.cg.shared.global [%0], [%1], 16;" :: "r"(saddr), "l"(gptr));
}
__device__ __forceinline__ void cp_commit() {
    asm volatile("cp.async.commit_group;");
}
template<int N> __device__ __forceinline__ void cp_wait() {
    asm volatile("cp.async.wait_group %0;" :: "n"(N));
}

__device__ __forceinline__ void mma_tf32(float* d, const uint32_t* a, const uint32_t* b) {
    asm volatile(
        "mma.sync.aligned.m16n8k8.row.col.f32.tf32.tf32.f32 "
        "{%0,%1,%2,%3}, {%4,%5,%6,%7}, {%8,%9}, {%0,%1,%2,%3};"
        : "+f"(d[0]), "+f"(d[1]), "+f"(d[2]), "+f"(d[3])
        : "r"(a[0]), "r"(a[1]), "r"(a[2]), "r"(a[3]), "r"(b[0]), "r"(b[1]));
}

__device__ __forceinline__ void tf32_gemm_main(const uint32_t* __restrict__ A,
                                               const uint32_t* __restrict__ W,
                                               int K, float acc[4][4][4])
{
    extern __shared__ uint32_t dsm[];
    const int row0 = blockIdx.y * 128;
    const int col0 = blockIdx.x * 128;
    const int tid  = threadIdx.x;
    const int lane = tid & 31;
    const int warp = tid >> 5;
    const int wm = warp >> 2;
    const int wn = warp & 3;
    const int gid = lane >> 2;
    const int tig = lane & 3;

    const int lr = tid >> 1;
    const int lc = (tid & 1) * 8;

    const uint32_t* Ag = A + (size_t)(row0 + lr) * K + lc;
    const uint32_t* Wg = W + (size_t)(col0 + lr) * K + lc;

    uint32_t smem_base = (uint32_t)__cvta_generic_to_shared(dsm);
    const uint32_t a_dst = smem_base + (uint32_t)(lr * 20 + lc) * 4;
    const uint32_t b_dst = a_dst + 128 * 20 * 4;

    const int NITER = K >> 4;

#pragma unroll
    for (int i = 0; i < 4; i++)
#pragma unroll
        for (int j = 0; j < 4; j++)
#pragma unroll
            for (int r = 0; r < 4; r++) acc[i][j][r] = 0.f;

#pragma unroll
    for (int s = 0; s < GSTAGES - 1; s++) {
        uint32_t so = (uint32_t)(s * STAGE_ELEMS) * 4;
        cp_async16(a_dst + so,      Ag + s * 16);
        cp_async16(a_dst + so + 16, Ag + s * 16 + 4);
        cp_async16(b_dst + so,      Wg + s * 16);
        cp_async16(b_dst + so + 16, Wg + s * 16 + 4);
        cp_commit();
    }

    for (int it = 0; it < NITER; it++) {
        cp_wait<GSTAGES - 2>();
        __syncthreads();

        int nxt = it + GSTAGES - 1;
        if (nxt < NITER) {
            int s = nxt & (GSTAGES - 1);
            uint32_t so = (uint32_t)(s * STAGE_ELEMS) * 4;
            cp_async16(a_dst + so,      Ag + nxt * 16);
            cp_async16(a_dst + so + 16, Ag + nxt * 16 + 4);
            cp_async16(b_dst + so,      Wg + nxt * 16);
            cp_async16(b_dst + so + 16, Wg + nxt * 16 + 4);
        }
        cp_commit();

        const uint32_t* As = dsm + (it & (GSTAGES - 1)) * STAGE_ELEMS;
        const uint32_t* Bs = As + 128 * 20;

#pragma unroll
        for (int kk = 0; kk < 16; kk += 8) {
            uint32_t af[4][4], bf[4][2];
#pragma unroll
            for (int mt = 0; mt < 4; mt++) {
                int r = wm * 64 + mt * 16 + gid;
                af[mt][0] = As[r * 20 + kk + tig];
                af[mt][1] = As[(r + 8) * 20 + kk + tig];
                af[mt][2] = As[r * 20 + kk + tig + 4];
                af[mt][3] = As[(r + 8) * 20 + kk + tig + 4];
            }
#pragma unroll
            for (int nt = 0; nt < 4; nt++) {
                int cb = wn * 32 + nt * 8 + gid;
                bf[nt][0] = Bs[cb * 20 + kk + tig];
                bf[nt][1] = Bs[cb * 20 + kk + tig + 4];
            }
#pragma unroll
            for (int mt = 0; mt < 4; mt++)
#pragma unroll
                for (int nt = 0; nt < 4; nt++)
                    mma_tf32(acc[mt][nt], af[mt], bf[nt]);
        }
    }
}

__global__ void __launch_bounds__(256, 2) gemm_qkv()
{
    float acc[4][4][4];
    tf32_gemm_main(g_xt, g_qkvw_t, DIM, acc);

    const int row0 = blockIdx.y * 128;
    const int col0 = blockIdx.x * 128;
    const int tid  = threadIdx.x;
    const int lane = tid & 31;
    const int warp = tid >> 5;
    const int wm = warp >> 2, wn = warp & 3;
    const int gid = lane >> 2, tig = lane & 3;

    float* C;
    int ldc, cbase;
    if (col0 < DIM) { C = g_q;  ldc = DIM;     cbase = col0; }
    else            { C = g_kv; ldc = 2 * DIM; cbase = col0 - DIM; }

#pragma unroll
    for (int mt = 0; mt < 4; mt++) {
        int r = row0 + wm * 64 + mt * 16 + gid;
#pragma unroll
        for (int nt = 0; nt < 4; nt++) {
            int c = cbase + wn * 32 + nt * 8 + 2 * tig;
            *(float2*)&C[(size_t)r * ldc + c]       = make_float2(acc[mt][nt][0], acc[mt][nt][1]);
            *(float2*)&C[(size_t)(r + 8) * ldc + c] = make_float2(acc[mt][nt][2], acc[mt][nt][3]);
        }
    }
}

__global__ void __launch_bounds__(256, 2) gemm_proj(const float* __restrict__ bias,
                                                    float* __restrict__ out)
{
    float acc[4][4][4];
    tf32_gemm_main(g_attn_t, g_pw_t, DIM, acc);

    const int row0 = blockIdx.y * 128;
    const int col0 = blockIdx.x * 128;
    const int tid  = threadIdx.x;
    const int lane = tid & 31;
    const int warp = tid >> 5;
    const int wm = warp >> 2, wn = warp & 3;
    const int gid = lane >> 2, tig = lane & 3;

#pragma unroll
    for (int mt = 0; mt < 4; mt++) {
        int r = row0 + wm * 64 + mt * 16 + gid;
#pragma unroll
        for (int nt = 0; nt < 4; nt++) {
            int c = col0 + wn * 32 + nt * 8 + 2 * tig;
            float2 bb = *(const float2*)&bias[c];
            *(float2*)&out[(size_t)r * DIM + c] =
                make_float2(acc[mt][nt][0] + bb.x, acc[mt][nt][1] + bb.y);
            *(float2*)&out[(size_t)(r + 8) * DIM + c] =
                make_float2(acc[mt][nt][2] + bb.x, acc[mt][nt][3] + bb.y);
        }
    }
}

// ======================= bias precompute =======================
__device__ __forceinline__ float bilin7(const float* __restrict__ t, int i, int j)
{
    float si = (i - 1.5f) * 0.25f;
    float sj = (j - 1.5f) * 0.25f;
    float fi = floorf(si), fj = floorf(sj);
    int i0 = (int)fi, j0 = (int)fj;
    float wi = si - fi, wj = sj - fj;
    int i0c = max(0, min(6, i0)), i1c = max(0, min(6, i0 + 1));
    int j0c = max(0, min(6, j0)), j1c = max(0, min(6, j0 + 1));
    float v00 = t[i0c * 7 + j0c], v01 = t[i0c * 7 + j1c];
    float v10 = t[i1c * 7 + j0c], v11 = t[i1c * 7 + j1c];
    return (1.f - wi) * ((1.f - wj) * v00 + wj * v01)
         +        wi  * ((1.f - wj) * v10 + wj * v11);
}

__global__ void build_bias(const float* __restrict__ an_bias, const float* __restrict__ na_bias,
                           const float* __restrict__ ah_bias, const float* __restrict__ aw_bias,
                           const float* __restrict__ ha_bias, const float* __restrict__ wa_bias)
{
    int ha = blockIdx.x;
    int h = ha / DA, a = ha % DA;
    int n = threadIdx.x;
    int i = n / WW, j = n % WW;
    g_pos_bias[(size_t)ha * NTOK + n] =
        bilin7(an_bias + (size_t)ha * 49, i, j) + ah_bias[ha * HH + i] + aw_bias[ha * WW + j];
    g_agent_bias_t[(size_t)ha * NTOK + n] =
        bilin7(na_bias + (size_t)ha * 49, i, j)
        + ha_bias[(h * HH + i) * DA + a] + wa_bias[(h * WW + j) * DA + a];
}

// ======================= fused attention (pool + agent-attn + q-attn) =======================
// one block per (b,h), 512 threads
// dyn smem: sS[49][784] + sAg[49][64] + sAV[49][64]
#define FA_SMEM_BYTES ((DA * NTOK + 2 * DA * HD) * 4)   // 178752

__global__ void __launch_bounds__(512, 1) fused_attn()
{
    extern __shared__ float sm[];
    float* sS  = sm;                       // [49][784]
    float* sAg = sm + DA * NTOK;           // [49][64]  (agent * scale)
    float* sAV = sAg + DA * HD;            // [49][64]
    __shared__ float sInv[DA];
    const int h = blockIdx.x, b = blockIdx.y;
    const int tid = threadIdx.x;
    const int warp = tid >> 5, lane = tid & 31;

    // ---- P0: pooled agent (4x4 avg of q image), scaled by 0.125 ----
    for (int i = tid; i < DA * HD; i += 512) {
        int a = i >> 6, d = i & 63;
        int ai = a / 7, aj = a % 7;
        const float* qb = g_q + ((size_t)b * NTOK + (ai * 4) * WW + aj * 4) * DIM + h * HD + d;
        float s = 0.f;
#pragma unroll
        for (int di = 0; di < 4; di++)
#pragma unroll
            for (int dj = 0; dj < 4; dj++)
                s += qb[(di * WW + dj) * DIM];
        sAg[i] = s * (0.0625f * 0.125f);
    }
    __syncthreads();

    // ---- P1: agent scores S[a][n] = sAg[a].k[n] + pos_bias ----
    for (int n = tid; n < NTOK; n += 512) {
        u64 kp[32];
        const ulonglong2* kr = (const ulonglong2*)(g_kv + ((size_t)(b * NTOK + n)) * (2 * DIM) + h * HD);
#pragma unroll
        for (int i = 0; i < 16; i++) {
            ulonglong2 v = kr[i];
            kp[2 * i] = v.x; kp[2 * i + 1] = v.y;
        }
        const float* pb = g_pos_bias + (size_t)h * DA * NTOK + n;
        for (int a = 0; a < DA; a++) {
            const ulonglong2* Ar = (const ulonglong2*)&sAg[a * HD];
            u64 acc0 = 0, acc1 = 0;
#pragma unroll
            for (int i = 0; i < 16; i++) {
                ulonglong2 av = Ar[i];
                fma2(acc0, kp[2 * i], av.x);
                fma2(acc1, kp[2 * i + 1], av.y);
            }
            float2 f0 = unpack2(acc0), f1 = unpack2(acc1);
            sS[a * NTOK + n] = (f0.x + f0.y) + (f1.x + f1.y) + pb[a * NTOK];
        }
    }
    __syncthreads();

    // ---- P2: row softmax over n (warp per agent row) ----
    for (int a = warp; a < DA; a += 16) {
        float* row = sS + a * NTOK;
        float m = -1e30f;
        for (int n = lane; n < NTOK; n += 32) m = fmaxf(m, row[n]);
#pragma unroll
        for (int o = 16; o > 0; o >>= 1) m = fmaxf(m, __shfl_xor_sync(0xffffffff, m, o));
        float s = 0.f;
        for (int n = lane; n < NTOK; n += 32) { float e = __expf(row[n] - m); row[n] = e; s += e; }
#pragma unroll
        for (int o = 16; o > 0; o >>= 1) s += __shfl_xor_sync(0xffffffff, s, o);
        if (lane == 0) sInv[a] = 1.f / s;
    }
    __syncthreads();

    // ---- P3: agent_v[a][d] = (P[a] @ V)[d] * inv[a]  -> sAV ----
    // 16 groups of 32 threads; thread owns d-pair (lane*2, lane*2+1); group owns a = warp + 16*i
    {
        u64 acc[4];
#pragma unroll
        for (int i = 0; i < 4; i++) acc[i] = 0;
        const float* vb = g_kv + (size_t)b * NTOK * (2 * DIM) + DIM + h * HD + lane * 2;
        for (int n = 0; n < NTOK; n++) {
            u64 vv = *(const u64*)(vb + (size_t)n * (2 * DIM));
#pragma unroll
            for (int i = 0; i < 4; i++) {
                int a = warp + 16 * i;
                if (a < DA) {
                    float p = sS[a * NTOK + n];
                    fma2(acc[i], pack2(p, p), vv);
                }
            }
        }
#pragma unroll
        for (int i = 0; i < 4; i++) {
            int a = warp + 16 * i;
            if (a < DA) {
                float2 f = unpack2(acc[i]);
                float inv = sInv[a];
                sAV[a * HD + lane * 2]     = f.x * inv;
                sAV[a * HD + lane * 2 + 1] = f.y * inv;
            }
        }
    }
    __syncthreads();

    // ---- P4: q attention; per-thread score row staged in sS scratch ----
    float* row = sS + tid * DA;            // 512*49 <= 49*784, conflict-free (49 mod 32 = 17)
    for (int n = tid; n < NTOK; n += 512) {
        u64 qp[32];
        const ulonglong2* qpt = (const ulonglong2*)(g_q + ((size_t)(b * NTOK + n)) * DIM + h * HD);
#pragma unroll
        for (int i = 0; i < 16; i++) {
            ulonglong2 v = qpt[i];
            qp[2 * i] = v.x; qp[2 * i + 1] = v.y;
        }
        const float* abT = g_agent_bias_t + (size_t)h * DA * NTOK + n;
        float m = -1e30f;
        for (int a = 0; a < DA; a++) {
            const ulonglong2* Ar = (const ulonglong2*)&sAg[a * HD];
            u64 acc0 = 0, acc1 = 0;
#pragma unroll
            for (int i = 0; i < 16; i++) {
                ulonglong2 av = Ar[i];
                fma2(acc0, qp[2 * i], av.x);
                fma2(acc1, qp[2 * i + 1], av.y);
            }
            float2 f0 = unpack2(acc0), f1 = unpack2(acc1);
            float s = (f0.x + f0.y) + (f1.x + f1.y) + abT[a * NTOK];
            row[a] = s;
            m = fmaxf(m, s);
        }

        float sum = 0.f;
        for (int a = 0; a < DA; a++) { float e = __expf(row[a] - m); row[a] = e; sum += e; }
        float inv = 1.f / sum;

        u64 o[32];
#pragma unroll
        for (int i = 0; i < 32; i++) o[i] = 0;
        for (int a = 0; a < DA; a++) {
            float p = row[a] * inv;
            u64 pp = pack2(p, p);
            const ulonglong2* Vr = (const ulonglong2*)&sAV[a * HD];
#pragma unroll
            for (int i = 0; i < 16; i++) {
                ulonglong2 vv = Vr[i];
                fma2(o[2 * i], pp, vv.x);
                fma2(o[2 * i + 1], pp, vv.y);
            }
        }
        float4* op = (float4*)(g_attn + ((size_t)(b * NTOK + n)) * DIM + h * HD);
#pragma unroll
        for (int i = 0; i < 16; i++) {
            float2 lo = unpack2(o[2 * i]), hi = unpack2(o[2 * i + 1]);
            op[i] = make_float4(lo.x, lo.y, hi.x, hi.y);
        }
    }
}

// ======================= depthwise 3x3 conv on v, + attn, -> tf32 =======================
__global__ void dwc_add(const float* __restrict__ w, const float* __restrict__ bias)
{
    int n = blockIdx.x, b = blockIdx.y;
    int c = threadIdx.x;
    int i = n / WW, j = n % WW;
    float acc = bias[c];
#pragma unroll
    for (int di = 0; di < 3; di++) {
        int ii = i + di - 1;
        if (ii < 0 || ii > HH - 1) continue;
#pragma unroll
        for (int dj = 0; dj < 3; dj++) {
            int jj = j + dj - 1;
            if (jj < 0 || jj > WW - 1) continue;
            acc = fmaf(w[c * 9 + di * 3 + dj],
                       g_kv[((size_t)(b * NTOK + ii * WW + jj)) * (2 * DIM) + DIM + c], acc);
        }
    }
    size_t idx = ((size_t)(b * NTOK + n)) * DIM + c;
    g_attn_t[idx] = f2tf(g_attn[idx] + acc);
}

// ======================= launch =======================
extern "C" void kernel_launch(void* const* d_in, const int* in_sizes, int n_in,
                              void* d_out, int out_size)
{
    const float* x       = (const float*)d_in[0];
    const float* q_w     = (const float*)d_in[1];
    const float* kv_w    = (const float*)d_in[2];
    const float* proj_w  = (const float*)d_in[3];
    const float* proj_b  = (const float*)d_in[4];
    const float* dwc_w   = (const float*)d_in[5];
    const float* dwc_b   = (const float*)d_in[6];
    const float* an_bias = (const float*)d_in[7];
    const float* na_bias = (const float*)d_in[8];
    const float* ah_bias = (const float*)d_in[9];
    const float* aw_bias = (const float*)d_in[10];
    const float* ha_bias = (const float*)d_in[11];
    const float* wa_bias = (const float*)d_in[12];
    float* out = (float*)d_out;

    cudaFuncSetAttribute(gemm_qkv,   cudaFuncAttributeMaxDynamicSharedMemorySize, GEMM_SMEM_BYTES);
    cudaFuncSetAttribute(gemm_proj,  cudaFuncAttributeMaxDynamicSharedMemorySize, GEMM_SMEM_BYTES);
    cudaFuncSetAttribute(fused_attn, cudaFuncAttributeMaxDynamicSharedMemorySize, FA_SMEM_BYTES);

    // 1: convert everything to tf32
    cvt_all<<<dim3(512, 4), 256>>>((const float4*)x, (const float4*)q_w,
                                   (const float4*)kv_w, (const float4*)proj_w);
    // 2: merged QKV GEMM
    gemm_qkv<<<dim3(3 * DIM / 128, (BATCH * NTOK) / 128), 256, GEMM_SMEM_BYTES>>>();
    // 3: bias tables
    build_bias<<<NH * DA, NTOK>>>(an_bias, na_bias, ah_bias, aw_bias, ha_bias, wa_bias);
    // 4: fused attention  <-- ncu-profiled slot
    fused_attn<<<dim3(NH, BATCH), 512, FA_SMEM_BYTES>>>();
    // 5: depthwise conv + add + tf32 convert
    dwc_add<<<dim3(NTOK, BATCH), DIM>>>(dwc_w, dwc_b);
    // 6: output projection
    gemm_proj<<<dim3(DIM / 128, (BATCH * NTOK) / 128), 256, GEMM_SMEM_BYTES>>>(proj_b, out);
}

// round 8
// speedup vs baseline: 1.6760x; 1.0568x over previous
#include <cuda_runtime.h>
#include <math.h>
#include <stdint.h>

// Problem constants
#define BATCH 32
#define NTOK  784
#define DIM   512
#define NH    8
#define HD    64
#define HH    28
#define WW    28
#define DA    49

typedef unsigned long long u64;

// -------- scratch (__device__ globals; no allocations allowed) --------
// head-planar activations: [b][h][n][d]
__device__ float    g_qh[BATCH * NH * NTOK * HD];
__device__ float    g_k [BATCH * NH * NTOK * HD];
__device__ float    g_v [BATCH * NH * NTOK * HD];
__device__ float    g_pos_bias[NH * DA * NTOK];        // [h,a,n]
__device__ float    g_agent_bias_t[NH * DA * NTOK];    // [h,a,n]
__device__ float    g_attn [BATCH * NTOK * DIM];       // [b][n][c] staging (pre-dwc)
__device__ uint32_t g_xt   [BATCH * NTOK * DIM];
__device__ uint32_t g_qkvw_t[3 * DIM * DIM];           // q_w then kv_w [1536][512]
__device__ uint32_t g_pw_t [DIM * DIM];
__device__ uint32_t g_attn_t[BATCH * NTOK * DIM];

__device__ __forceinline__ uint32_t f2tf(float f) {
    uint32_t u;
    asm("cvt.rna.tf32.f32 %0, %1;" : "=r"(u) : "f"(f));
    return u;
}
__device__ __forceinline__ void fma2(u64& d, u64 a, u64 b) {
    asm("fma.rn.f32x2 %0, %1, %2, %0;" : "+l"(d) : "l"(a), "l"(b));
}
__device__ __forceinline__ float2 unpack2(u64 v) {
    float2 f;
    asm("mov.b64 {%0,%1}, %2;" : "=f"(f.x), "=f"(f.y) : "l"(v));
    return f;
}
__device__ __forceinline__ u64 pack2(float lo, float hi) {
    u64 r;
    asm("mov.b64 %0, {%1,%2};" : "=l"(r) : "f"(lo), "f"(hi));
    return r;
}

// ======================= fp32 -> tf32 conversion (all operands, one kernel) =======================
__global__ void cvt_all(const float4* __restrict__ x, const float4* __restrict__ qw,
                        const float4* __restrict__ kvw, const float4* __restrict__ pw)
{
    const float4* src;
    uint4* dst;
    int n4;
    switch (blockIdx.y) {
        case 0: src = x;   dst = (uint4*)g_xt;                 n4 = BATCH * NTOK * DIM / 4; break;
        case 1: src = qw;  dst = (uint4*)g_qkvw_t;             n4 = DIM * DIM / 4;          break;
        case 2: src = kvw; dst = (uint4*)(g_qkvw_t + DIM*DIM); n4 = 2 * DIM * DIM / 4;      break;
        default: src = pw; dst = (uint4*)g_pw_t;               n4 = DIM * DIM / 4;          break;
    }
    for (int i = blockIdx.x * blockDim.x + threadIdx.x; i < n4; i += gridDim.x * blockDim.x) {
        float4 v = src[i];
        uint4 o;
        o.x = f2tf(v.x); o.y = f2tf(v.y); o.z = f2tf(v.z); o.w = f2tf(v.w);
        dst[i] = o;
    }
}

// ======================= TF32 tensor-core GEMM, cp.async 4-stage =======================
#define GSTAGES 4
#define STAGE_ELEMS (2 * 128 * 20)
#define GEMM_SMEM_BYTES (GSTAGES * STAGE_ELEMS * 4)   // 81920

__device__ __forceinline__ void cp_async16(uint32_t saddr, const void* gptr) {
    asm volatile("cp.async.cg.shared.global [%0], [%1], 16;" :: "r"(saddr), "l"(gptr));
}
__device__ __forceinline__ void cp_commit() {
    asm volatile("cp.async.commit_group;");
}
template<int N> __device__ __forceinline__ void cp_wait() {
    asm volatile("cp.async.wait_group %0;" :: "n"(N));
}

__device__ __forceinline__ void mma_tf32(float* d, const uint32_t* a, const uint32_t* b) {
    asm volatile(
        "mma.sync.aligned.m16n8k8.row.col.f32.tf32.tf32.f32 "
        "{%0,%1,%2,%3}, {%4,%5,%6,%7}, {%8,%9}, {%0,%1,%2,%3};"
        : "+f"(d[0]), "+f"(d[1]), "+f"(d[2]), "+f"(d[3])
        : "r"(a[0]), "r"(a[1]), "r"(a[2]), "r"(a[3]), "r"(b[0]), "r"(b[1]));
}

__device__ __forceinline__ void tf32_gemm_main(const uint32_t* __restrict__ A,
                                               const uint32_t* __restrict__ W,
                                               int K, float acc[4][4][4])
{
    extern __shared__ uint32_t dsm[];
    const int row0 = blockIdx.y * 128;
    const int col0 = blockIdx.x * 128;
    const int tid  = threadIdx.x;
    const int lane = tid & 31;
    const int warp = tid >> 5;
    const int wm = warp >> 2;
    const int wn = warp & 3;
    const int gid = lane >> 2;
    const int tig = lane & 3;

    const int lr = tid >> 1;
    const int lc = (tid & 1) * 8;

    const uint32_t* Ag = A + (size_t)(row0 + lr) * K + lc;
    const uint32_t* Wg = W + (size_t)(col0 + lr) * K + lc;

    uint32_t smem_base = (uint32_t)__cvta_generic_to_shared(dsm);
    const uint32_t a_dst = smem_base + (uint32_t)(lr * 20 + lc) * 4;
    const uint32_t b_dst = a_dst + 128 * 20 * 4;

    const int NITER = K >> 4;

#pragma unroll
    for (int i = 0; i < 4; i++)
#pragma unroll
        for (int j = 0; j < 4; j++)
#pragma unroll
            for (int r = 0; r < 4; r++) acc[i][j][r] = 0.f;

#pragma unroll
    for (int s = 0; s < GSTAGES - 1; s++) {
        uint32_t so = (uint32_t)(s * STAGE_ELEMS) * 4;
        cp_async16(a_dst + so,      Ag + s * 16);
        cp_async16(a_dst + so + 16, Ag + s * 16 + 4);
        cp_async16(b_dst + so,      Wg + s * 16);
        cp_async16(b_dst + so + 16, Wg + s * 16 + 4);
        cp_commit();
    }

    for (int it = 0; it < NITER; it++) {
        cp_wait<GSTAGES - 2>();
        __syncthreads();

        int nxt = it + GSTAGES - 1;
        if (nxt < NITER) {
            int s = nxt & (GSTAGES - 1);
            uint32_t so = (uint32_t)(s * STAGE_ELEMS) * 4;
            cp_async16(a_dst + so,      Ag + nxt * 16);
            cp_async16(a_dst + so + 16, Ag + nxt * 16 + 4);
            cp_async16(b_dst + so,      Wg + nxt * 16);
            cp_async16(b_dst + so + 16, Wg + nxt * 16 + 4);
        }
        cp_commit();

        const uint32_t* As = dsm + (it & (GSTAGES - 1)) * STAGE_ELEMS;
        const uint32_t* Bs = As + 128 * 20;

#pragma unroll
        for (int kk = 0; kk < 16; kk += 8) {
            uint32_t af[4][4], bf[4][2];
#pragma unroll
            for (int mt = 0; mt < 4; mt++) {
                int r = wm * 64 + mt * 16 + gid;
                af[mt][0] = As[r * 20 + kk + tig];
                af[mt][1] = As[(r + 8) * 20 + kk + tig];
                af[mt][2] = As[r * 20 + kk + tig + 4];
                af[mt][3] = As[(r + 8) * 20 + kk + tig + 4];
            }
#pragma unroll
            for (int nt = 0; nt < 4; nt++) {
                int cb = wn * 32 + nt * 8 + gid;
                bf[nt][0] = Bs[cb * 20 + kk + tig];
                bf[nt][1] = Bs[cb * 20 + kk + tig + 4];
            }
#pragma unroll
            for (int mt = 0; mt < 4; mt++)
#pragma unroll
                for (int nt = 0; nt < 4; nt++)
                    mma_tf32(acc[mt][nt], af[mt], bf[nt]);
        }
    }
}

// merged QKV GEMM; epilogue scatters into head-planar [b][h][n][d] arrays.
// col segment: 0..511 -> q, 512..1023 -> k, 1024..1535 -> v
__global__ void __launch_bounds__(256, 2) gemm_qkv()
{
    float acc[4][4][4];
    tf32_gemm_main(g_xt, g_qkvw_t, DIM, acc);

    const int row0 = blockIdx.y * 128;
    const int col0 = blockIdx.x * 128;
    const int tid  = threadIdx.x;
    const int lane = tid & 31;
    const int warp = tid >> 5;
    const int wm = warp >> 2, wn = warp & 3;
    const int gid = lane >> 2, tig = lane & 3;

    const int seg = col0 >> 9;                 // 0=q,1=k,2=v (tile never straddles)
    float* P = (seg == 0) ? g_qh : (seg == 1) ? g_k : g_v;
    const int cseg = col0 & 511;

#pragma unroll
    for (int mt = 0; mt < 4; mt++) {
        int r  = row0 + wm * 64 + mt * 16 + gid;
        int bb = r / NTOK, nn = r % NTOK;
        int r8 = r + 8;
        int bb8 = r8 / NTOK, nn8 = r8 % NTOK;
#pragma unroll
        for (int nt = 0; nt < 4; nt++) {
            int c = cseg + wn * 32 + nt * 8 + 2 * tig;
            int h = c >> 6, d = c & 63;
            *(float2*)&P[(((size_t)(bb * NH + h)) * NTOK + nn) * HD + d] =
                make_float2(acc[mt][nt][0], acc[mt][nt][1]);
            *(float2*)&P[(((size_t)(bb8 * NH + h)) * NTOK + nn8) * HD + d] =
                make_float2(acc[mt][nt][2], acc[mt][nt][3]);
        }
    }
}

__global__ void __launch_bounds__(256, 2) gemm_proj(const float* __restrict__ bias,
                                                    float* __restrict__ out)
{
    float acc[4][4][4];
    tf32_gemm_main(g_attn_t, g_pw_t, DIM, acc);

    const int row0 = blockIdx.y * 128;
    const int col0 = blockIdx.x * 128;
    const int tid  = threadIdx.x;
    const int lane = tid & 31;
    const int warp = tid >> 5;
    const int wm = warp >> 2, wn = warp & 3;
    const int gid = lane >> 2, tig = lane & 3;

#pragma unroll
    for (int mt = 0; mt < 4; mt++) {
        int r = row0 + wm * 64 + mt * 16 + gid;
#pragma unroll
        for (int nt = 0; nt < 4; nt++) {
            int c = col0 + wn * 32 + nt * 8 + 2 * tig;
            float2 bb = *(const float2*)&bias[c];
            *(float2*)&out[(size_t)r * DIM + c] =
                make_float2(acc[mt][nt][0] + bb.x, acc[mt][nt][1] + bb.y);
            *(float2*)&out[(size_t)(r + 8) * DIM + c] =
                make_float2(acc[mt][nt][2] + bb.x, acc[mt][nt][3] + bb.y);
        }
    }
}

// ======================= bias precompute =======================
__device__ __forceinline__ float bilin7(const float* __restrict__ t, int i, int j)
{
    float si = (i - 1.5f) * 0.25f;
    float sj = (j - 1.5f) * 0.25f;
    float fi = floorf(si), fj = floorf(sj);
    int i0 = (int)fi, j0 = (int)fj;
    float wi = si - fi, wj = sj - fj;
    int i0c = max(0, min(6, i0)), i1c = max(0, min(6, i0 + 1));
    int j0c = max(0, min(6, j0)), j1c = max(0, min(6, j0 + 1));
    float v00 = t[i0c * 7 + j0c], v01 = t[i0c * 7 + j1c];
    float v10 = t[i1c * 7 + j0c], v11 = t[i1c * 7 + j1c];
    return (1.f - wi) * ((1.f - wj) * v00 + wj * v01)
         +        wi  * ((1.f - wj) * v10 + wj * v11);
}

__global__ void build_bias(const float* __restrict__ an_bias, const float* __restrict__ na_bias,
                           const float* __restrict__ ah_bias, const float* __restrict__ aw_bias,
                           const float* __restrict__ ha_bias, const float* __restrict__ wa_bias)
{
    int ha = blockIdx.x;
    int h = ha / DA, a = ha % DA;
    int n = threadIdx.x;
    int i = n / WW, j = n % WW;
    g_pos_bias[(size_t)ha * NTOK + n] =
        bilin7(an_bias + (size_t)ha * 49, i, j) + ah_bias[ha * HH + i] + aw_bias[ha * WW + j];
    g_agent_bias_t[(size_t)ha * NTOK + n] =
        bilin7(na_bias + (size_t)ha * 49, i, j)
        + ha_bias[(h * HH + i) * DA + a] + wa_bias[(h * WW + j) * DA + a];
}

// ======================= fused attention (pool + agent-attn + q-attn) =======================
// one block per (b,h), 512 threads
// dyn smem: sS[49][784] + sAg[49][64] + sAV[49][64]
#define FA_SMEM_BYTES ((DA * NTOK + 2 * DA * HD) * 4)   // 178752

__global__ void __launch_bounds__(512, 1) fused_attn()
{
    extern __shared__ float sm[];
    float* sS  = sm;                       // [49][784]
    float* sAg = sm + DA * NTOK;           // [49][64]  (agent * scale)
    float* sAV = sAg + DA * HD;            // [49][64]
    __shared__ float sInv[DA];
    const int h = blockIdx.x, b = blockIdx.y;
    const int tid = threadIdx.x;
    const int warp = tid >> 5, lane = tid & 31;

    const float* qpl = g_qh + ((size_t)(b * NH + h)) * NTOK * HD;   // q plane [n][d]
    const float* kpl = g_k  + ((size_t)(b * NH + h)) * NTOK * HD;
    const float* vpl = g_v  + ((size_t)(b * NH + h)) * NTOK * HD;

    // ---- P0: pooled agent (4x4 avg over q image), scaled by 0.125 ----
    for (int i = tid; i < DA * HD; i += 512) {
        int a = i >> 6, d = i & 63;
        int ai = a / 7, aj = a % 7;
        const float* qb = qpl + ((ai * 4) * WW + aj * 4) * HD + d;
        float s = 0.f;
#pragma unroll
        for (int di = 0; di < 4; di++)
#pragma unroll
            for (int dj = 0; dj < 4; dj++)
                s += qb[(di * WW + dj) * HD];
        sAg[i] = s * (0.0625f * 0.125f);
    }
    __syncthreads();

    // ---- P1: agent scores S[a][n] = sAg[a].k[n] + pos_bias ----
    for (int n = tid; n < NTOK; n += 512) {
        u64 kp[32];
        const ulonglong2* kr = (const ulonglong2*)(kpl + (size_t)n * HD);
#pragma unroll
        for (int i = 0; i < 16; i++) {
            ulonglong2 v = kr[i];
            kp[2 * i] = v.x; kp[2 * i + 1] = v.y;
        }
        const float* pb = g_pos_bias + (size_t)h * DA * NTOK + n;
        for (int a = 0; a < DA; a++) {
            const ulonglong2* Ar = (const ulonglong2*)&sAg[a * HD];
            u64 acc0 = 0, acc1 = 0;
#pragma unroll
            for (int i = 0; i < 16; i++) {
                ulonglong2 av = Ar[i];
                fma2(acc0, kp[2 * i], av.x);
                fma2(acc1, kp[2 * i + 1], av.y);
            }
            float2 f0 = unpack2(acc0), f1 = unpack2(acc1);
            sS[a * NTOK + n] = (f0.x + f0.y) + (f1.x + f1.y) + pb[a * NTOK];
        }
    }
    __syncthreads();

    // ---- P2: row softmax over n (warp per agent row) ----
    for (int a = warp; a < DA; a += 16) {
        float* row = sS + a * NTOK;
        float m = -1e30f;
        for (int n = lane; n < NTOK; n += 32) m = fmaxf(m, row[n]);
#pragma unroll
        for (int o = 16; o > 0; o >>= 1) m = fmaxf(m, __shfl_xor_sync(0xffffffff, m, o));
        float s = 0.f;
        for (int n = lane; n < NTOK; n += 32) { float e = __expf(row[n] - m); row[n] = e; s += e; }
#pragma unroll
        for (int o = 16; o > 0; o >>= 1) s += __shfl_xor_sync(0xffffffff, s, o);
        if (lane == 0) sInv[a] = 1.f / s;
    }
    __syncthreads();

    // ---- P3: agent_v[a][d] = (P[a] @ V)[d] * inv[a]  -> sAV ----
    // 16 warps; thread owns d-pair (2*lane); warp covers a = warp, warp+16, ...
    {
        u64 acc[4];
#pragma unroll
        for (int i = 0; i < 4; i++) acc[i] = 0;
        const float* vb = vpl + lane * 2;
#pragma unroll 4
        for (int n = 0; n < NTOK; n++) {
            u64 vv = *(const u64*)(vb + (size_t)n * HD);
#pragma unroll
            for (int i = 0; i < 4; i++) {
                int a = warp + 16 * i;
                if (a < DA) {
                    float p = sS[a * NTOK + n];
                    fma2(acc[i], pack2(p, p), vv);
                }
            }
        }
#pragma unroll
        for (int i = 0; i < 4; i++) {
            int a = warp + 16 * i;
            if (a < DA) {
                float2 f = unpack2(acc[i]);
                float inv = sInv[a];
                sAV[a * HD + lane * 2]     = f.x * inv;
                sAV[a * HD + lane * 2 + 1] = f.y * inv;
            }
        }
    }
    __syncthreads();

    // ---- P4: q attention; per-thread score row staged in sS scratch ----
    float* row = sS + tid * DA;            // 512*49 <= 49*784
    for (int n = tid; n < NTOK; n += 512) {
        u64 qp[32];
        const ulonglong2* qpt = (const ulonglong2*)(qpl + (size_t)n * HD);
#pragma unroll
        for (int i = 0; i < 16; i++) {
            ulonglong2 v = qpt[i];
            qp[2 * i] = v.x; qp[2 * i + 1] = v.y;
        }
        const float* abT = g_agent_bias_t + (size_t)h * DA * NTOK + n;
        float m = -1e30f;
        for (int a = 0; a < DA; a++) {
            const ulonglong2* Ar = (const ulonglong2*)&sAg[a * HD];
            u64 acc0 = 0, acc1 = 0;
#pragma unroll
            for (int i = 0; i < 16; i++) {
                ulonglong2 av = Ar[i];
                fma2(acc0, qp[2 * i], av.x);
                fma2(acc1, qp[2 * i + 1], av.y);
            }
            float2 f0 = unpack2(acc0), f1 = unpack2(acc1);
            float s = (f0.x + f0.y) + (f1.x + f1.y) + abT[a * NTOK];
            row[a] = s;
            m = fmaxf(m, s);
        }

        float sum = 0.f;
        for (int a = 0; a < DA; a++) { float e = __expf(row[a] - m); row[a] = e; sum += e; }
        float inv = 1.f / sum;

        u64 o[32];
#pragma unroll
        for (int i = 0; i < 32; i++) o[i] = 0;
        for (int a = 0; a < DA; a++) {
            float p = row[a] * inv;
            u64 pp = pack2(p, p);
            const ulonglong2* Vr = (const ulonglong2*)&sAV[a * HD];
#pragma unroll
            for (int i = 0; i < 16; i++) {
                ulonglong2 vv = Vr[i];
                fma2(o[2 * i], pp, vv.x);
                fma2(o[2 * i + 1], pp, vv.y);
            }
        }
        float4* op = (float4*)(g_attn + ((size_t)(b * NTOK + n)) * DIM + h * HD);
#pragma unroll
        for (int i = 0; i < 16; i++) {
            float2 lo = unpack2(o[2 * i]), hi = unpack2(o[2 * i + 1]);
            op[i] = make_float4(lo.x, lo.y, hi.x, hi.y);
        }
    }
}

// ======================= depthwise 3x3 conv on v, + attn, -> tf32 =======================
__global__ void dwc_add(const float* __restrict__ w, const float* __restrict__ bias)
{
    int n = blockIdx.x, b = blockIdx.y;
    int c = threadIdx.x;
    int h = c >> 6, d = c & 63;
    int i = n / WW, j = n % WW;
    const float* vpl = g_v + ((size_t)(b * NH + h)) * NTOK * HD + d;
    float acc = bias[c];
#pragma unroll
    for (int di = 0; di < 3; di++) {
        int ii = i + di - 1;
        if (ii < 0 || ii > HH - 1) continue;
#pragma unroll
        for (int dj = 0; dj < 3; dj++) {
            int jj = j + dj - 1;
            if (jj < 0 || jj > WW - 1) continue;
            acc = fmaf(w[c * 9 + di * 3 + dj], vpl[(size_t)(ii * WW + jj) * HD], acc);
        }
    }
    size_t idx = ((size_t)(b * NTOK + n)) * DIM + c;
    g_attn_t[idx] = f2tf(g_attn[idx] + acc);
}

// ======================= launch =======================
extern "C" void kernel_launch(void* const* d_in, const int* in_sizes, int n_in,
                              void* d_out, int out_size)
{
    const float* x       = (const float*)d_in[0];
    const float* q_w     = (const float*)d_in[1];
    const float* kv_w    = (const float*)d_in[2];
    const float* proj_w  = (const float*)d_in[3];
    const float* proj_b  = (const float*)d_in[4];
    const float* dwc_w   = (const float*)d_in[5];
    const float* dwc_b   = (const float*)d_in[6];
    const float* an_bias = (const float*)d_in[7];
    const float* na_bias = (const float*)d_in[8];
    const float* ah_bias = (const float*)d_in[9];
    const float* aw_bias = (const float*)d_in[10];
    const float* ha_bias = (const float*)d_in[11];
    const float* wa_bias = (const float*)d_in[12];
    float* out = (float*)d_out;

    cudaFuncSetAttribute(gemm_qkv,   cudaFuncAttributeMaxDynamicSharedMemorySize, GEMM_SMEM_BYTES);
    cudaFuncSetAttribute(gemm_proj,  cudaFuncAttributeMaxDynamicSharedMemorySize, GEMM_SMEM_BYTES);
    cudaFuncSetAttribute(fused_attn, cudaFuncAttributeMaxDynamicSharedMemorySize, FA_SMEM_BYTES);

    // 1: convert everything to tf32
    cvt_all<<<dim3(512, 4), 256>>>((const float4*)x, (const float4*)q_w,
                                   (const float4*)kv_w, (const float4*)proj_w);
    // 2: merged QKV GEMM (head-planar epilogue)
    gemm_qkv<<<dim3(3 * DIM / 128, (BATCH * NTOK) / 128), 256, GEMM_SMEM_BYTES>>>();
    // 3: bias tables
    build_bias<<<NH * DA, NTOK>>>(an_bias, na_bias, ah_bias, aw_bias, ha_bias, wa_bias);
    // 4: fused attention  <-- ncu-profiled slot
    fused_attn<<<dim3(NH, BATCH), 512, FA_SMEM_BYTES>>>();
    // 5: depthwise conv + add + tf32 convert
    dwc_add<<<dim3(NTOK, BATCH), DIM>>>(dwc_w, dwc_b);
    // 6: output projection
    gemm_proj<<<dim3(DIM / 128, (BATCH * NTOK) / 128), 256, GEMM_SMEM_BYTES>>>(proj_b, out);
}